// round 6
// baseline (speedup 1.0000x reference)
#include <cuda_runtime.h>
#include <cstdint>
#include <stdint.h>
#include <math.h>

#define BB 256
#define SS 128
#define DIN 64
#define DOUT 64
#define HH 1024
#define H4 4096
#define NHEAD 4
#define HDIM 256
#define NSTEPS 16

// ---------------- scratch (static device allocations; no cudaMalloc) ----------------
__device__ float g_xT[SS * BB * DIN];
__device__ float g_pre[SS * BB * H4];
__device__ float g_y0[SS * BB * HH];
__device__ float g_y1[SS * BB * HH];
__device__ float g_Kp[SS * BB * HH];
__device__ float g_Vp[SS * BB * HH];
__device__ float g_z[BB * H4];
__device__ float g_c0[BB * HH];
__device__ float g_c1[BB * HH];
__device__ float g_zeros[BB * HH];
__device__ float g_dh0[2][BB * HH];
__device__ float g_dh1[2][BB * HH];
__device__ float g_q[BB * HH];
__device__ float g_ctx[BB * HH];
__device__ float g_att[BB * HH];
__device__ float g_comb[BB * HH];

// ---------------- small kernels ----------------
__device__ __forceinline__ float sigf(float x) { return 1.0f / (1.0f + expf(-x)); }

__global__ void k_zero3(float* a, float* b, float* c) {
    int i = blockIdx.x * blockDim.x + threadIdx.x;
    if (i < BB * HH) { a[i] = 0.f; b[i] = 0.f; c[i] = 0.f; }
}

__global__ void k_transpose_x(const float* __restrict__ x, float* __restrict__ xT) {
    int i = blockIdx.x * blockDim.x + threadIdx.x;
    if (i >= SS * BB * DIN) return;
    int k = i % DIN;
    int b = (i / DIN) % BB;
    int s = i / (DIN * BB);
    xT[i] = x[(b * SS + s) * DIN + k];
}

__global__ void k_gates(const float* __restrict__ z, const float* __restrict__ bias,
                        float* __restrict__ c, float* __restrict__ h) {
    int idx = blockIdx.x * blockDim.x + threadIdx.x;
    if (idx >= BB * HH) return;
    int b = idx >> 10;
    int j = idx & (HH - 1);
    const float* zb = z + b * H4;
    float gi = sigf(zb[j] + bias[j]);
    float gf = sigf(zb[HH + j] + bias[HH + j]);
    float gg = tanhf(zb[2 * HH + j] + bias[2 * HH + j]);
    float go = sigf(zb[3 * HH + j] + bias[3 * HH + j]);
    float cn = gf * c[idx] + gi * gg;
    c[idx] = cn;
    h[idx] = go * tanhf(cn);
}

// one block per (b, head); 256 threads (= HDIM)
__global__ void k_attn(const float* __restrict__ q, const float* __restrict__ Kp,
                       const float* __restrict__ Vp, float* __restrict__ ctx) {
    int b = blockIdx.x / NHEAD;
    int n = blockIdx.x % NHEAD;
    int tid = threadIdx.x;
    int lane = tid & 31;
    int warp = tid >> 5;

    __shared__ float qs[HDIM];
    __shared__ float sc[SS];
    __shared__ float red[8];

    qs[tid] = q[b * HH + n * HDIM + tid];
    __syncthreads();

    for (int s = warp; s < SS; s += 8) {
        const float* kp = Kp + ((size_t)s * BB + b) * HH + n * HDIM;
        float p = 0.f;
        #pragma unroll
        for (int d = lane; d < HDIM; d += 32) p += qs[d] * kp[d];
        #pragma unroll
        for (int o = 16; o > 0; o >>= 1) p += __shfl_xor_sync(0xffffffffu, p, o);
        if (lane == 0) sc[s] = p * (1.0f / 16.0f);
    }
    __syncthreads();

    float v = (tid < SS) ? sc[tid] : -1e30f;
    float m = v;
    #pragma unroll
    for (int o = 16; o > 0; o >>= 1) m = fmaxf(m, __shfl_xor_sync(0xffffffffu, m, o));
    if (lane == 0) red[warp] = m;
    __syncthreads();
    if (tid == 0) {
        float mm = red[0];
        #pragma unroll
        for (int w = 1; w < 8; w++) mm = fmaxf(mm, red[w]);
        red[0] = mm;
    }
    __syncthreads();
    float mx = red[0];
    float e = (tid < SS) ? expf(sc[tid] - mx) : 0.f;
    float ssum = e;
    #pragma unroll
    for (int o = 16; o > 0; o >>= 1) ssum += __shfl_xor_sync(0xffffffffu, ssum, o);
    __syncthreads();
    if (lane == 0) red[warp] = ssum;
    __syncthreads();
    if (tid == 0) {
        float t2 = 0.f;
        #pragma unroll
        for (int w = 0; w < 8; w++) t2 += red[w];
        red[0] = t2;
    }
    __syncthreads();
    float inv = 1.0f / red[0];
    if (tid < SS) sc[tid] = e * inv;
    __syncthreads();

    float acc = 0.f;
    const float* vb = Vp + (size_t)b * HH + n * HDIM + tid;
    for (int s = 0; s < SS; s++) acc += sc[s] * vb[(size_t)s * BB * HH];
    ctx[b * HH + n * HDIM + tid] = acc;
}

// ---------------- 3xTF32 tensor-core GEMM ----------------
// C = A@B [+Cadd][+bias][relu].  A row-major [M][lda], B row-major [K][ldb].
// Block tile 64x64, BK=32, 128 threads = 4 warps (2x2 of 32x32 warp tiles).
// Requires: M%64==0, N%64==0, K%32==0, 16B-aligned rows (true at all call sites).

__device__ __forceinline__ uint32_t cvt_tf32(float x) {
    uint32_t u;
    asm("cvt.rna.tf32.f32 %0, %1;" : "=r"(u) : "f"(x));
    return u;
}

__device__ __forceinline__ void mma8(float* d, const uint32_t* a, const uint32_t* b) {
    asm volatile(
        "mma.sync.aligned.m16n8k8.row.col.f32.tf32.tf32.f32 "
        "{%0,%1,%2,%3},{%4,%5,%6,%7},{%8,%9},{%0,%1,%2,%3};"
        : "+f"(d[0]), "+f"(d[1]), "+f"(d[2]), "+f"(d[3])
        : "r"(a[0]), "r"(a[1]), "r"(a[2]), "r"(a[3]), "r"(b[0]), "r"(b[1]));
}

__global__ void __launch_bounds__(128)
gemm_tf32x3(const float* __restrict__ A, int lda,
            const float* __restrict__ B, int ldb,
            float* __restrict__ C, int ldc,
            const float* __restrict__ Cadd,
            const float* __restrict__ bias,
            int K, int relu) {
    __shared__ float sAh[32][68];
    __shared__ float sAl[32][68];
    __shared__ float sBh[32][68];
    __shared__ float sBl[32][68];

    const int tid = threadIdx.x;
    const int lane = tid & 31;
    const int warp = tid >> 5;
    const int wm = warp >> 1;          // 0..1
    const int wn = warp & 1;           // 0..1
    const int g = lane >> 2;           // groupID 0..7
    const int tg = lane & 3;           // threadID_in_group 0..3
    const int row0 = blockIdx.y * 64;
    const int col0 = blockIdx.x * 64;

    // per-thread gmem mapping: A tile 64(m)x32(k) = 512 float4; B tile 32(k)x64(n)
    int am[4], ak[4], bk[4], bn[4];
    const float* ap[4];
    const float* bp[4];
    #pragma unroll
    for (int i = 0; i < 4; i++) {
        int f = tid + i * 128;
        am[i] = f >> 3;
        ak[i] = (f & 7) << 2;
        bk[i] = f >> 4;
        bn[i] = (f & 15) << 2;
        ap[i] = A + (size_t)(row0 + am[i]) * lda + ak[i];
        bp[i] = B + (size_t)bk[i] * ldb + col0 + bn[i];
    }

    float acc[2][4][4];
    #pragma unroll
    for (int i = 0; i < 2; i++)
        #pragma unroll
        for (int j = 0; j < 4; j++)
            #pragma unroll
            for (int e = 0; e < 4; e++) acc[i][j][e] = 0.f;

    // split fp32 -> (tf32 hi, tf32 lo) and stage into smem
    auto stage = [&](float4* va, float4* vb) {
        #pragma unroll
        for (int i = 0; i < 4; i++) {
            float xs[4] = {va[i].x, va[i].y, va[i].z, va[i].w};
            #pragma unroll
            for (int j2 = 0; j2 < 4; j2++) {
                float hi = __uint_as_float(cvt_tf32(xs[j2]));
                float lo = __uint_as_float(cvt_tf32(xs[j2] - hi));
                sAh[ak[i] + j2][am[i]] = hi;
                sAl[ak[i] + j2][am[i]] = lo;
            }
            float ys[4] = {vb[i].x, vb[i].y, vb[i].z, vb[i].w};
            float4 h4, l4;
            float* hp = &h4.x;
            float* lp = &l4.x;
            #pragma unroll
            for (int j2 = 0; j2 < 4; j2++) {
                float hi = __uint_as_float(cvt_tf32(ys[j2]));
                float lo = __uint_as_float(cvt_tf32(ys[j2] - hi));
                hp[j2] = hi;
                lp[j2] = lo;
            }
            *(float4*)&sBh[bk[i]][bn[i]] = h4;
            *(float4*)&sBl[bk[i]][bn[i]] = l4;
        }
    };

    const int nk = K >> 5;

    // prologue: chunk 0
    {
        float4 va[4], vb[4];
        #pragma unroll
        for (int i = 0; i < 4; i++) {
            va[i] = *(const float4*)ap[i];
            vb[i] = *(const float4*)bp[i];
        }
        stage(va, vb);
    }
    __syncthreads();

    for (int c = 0; c < nk; c++) {
        float4 va[4], vb[4];
        if (c + 1 < nk) {
            int k0 = (c + 1) << 5;
            #pragma unroll
            for (int i = 0; i < 4; i++) {
                va[i] = *(const float4*)(ap[i] + k0);
                vb[i] = *(const float4*)(bp[i] + (size_t)k0 * ldb);
            }
        }

        #pragma unroll
        for (int s = 0; s < 4; s++) {
            const int k8 = s * 8;
            uint32_t Ah[2][4], Al[2][4], Bh[4][2], Bl[4][2];
            #pragma unroll
            for (int i = 0; i < 2; i++) {
                int mb = wm * 32 + i * 16;
                Ah[i][0] = __float_as_uint(sAh[k8 + tg][mb + g]);
                Ah[i][1] = __float_as_uint(sAh[k8 + tg][mb + g + 8]);
                Ah[i][2] = __float_as_uint(sAh[k8 + tg + 4][mb + g]);
                Ah[i][3] = __float_as_uint(sAh[k8 + tg + 4][mb + g + 8]);
                Al[i][0] = __float_as_uint(sAl[k8 + tg][mb + g]);
                Al[i][1] = __float_as_uint(sAl[k8 + tg][mb + g + 8]);
                Al[i][2] = __float_as_uint(sAl[k8 + tg + 4][mb + g]);
                Al[i][3] = __float_as_uint(sAl[k8 + tg + 4][mb + g + 8]);
            }
            #pragma unroll
            for (int j = 0; j < 4; j++) {
                int nb = wn * 32 + j * 8;
                Bh[j][0] = __float_as_uint(sBh[k8 + tg][nb + g]);
                Bh[j][1] = __float_as_uint(sBh[k8 + tg + 4][nb + g]);
                Bl[j][0] = __float_as_uint(sBl[k8 + tg][nb + g]);
                Bl[j][1] = __float_as_uint(sBl[k8 + tg + 4][nb + g]);
            }
            #pragma unroll
            for (int i = 0; i < 2; i++)
                #pragma unroll
                for (int j = 0; j < 4; j++) {
                    mma8(acc[i][j], Ah[i], Bl[j]);
                    mma8(acc[i][j], Al[i], Bh[j]);
                    mma8(acc[i][j], Ah[i], Bh[j]);
                }
        }
        __syncthreads();
        if (c + 1 < nk) stage(va, vb);
        __syncthreads();
    }

    // epilogue
    #pragma unroll
    for (int i = 0; i < 2; i++) {
        int r = row0 + wm * 32 + i * 16 + g;
        #pragma unroll
        for (int j = 0; j < 4; j++) {
            int cc = col0 + wn * 32 + j * 8 + tg * 2;
            float v0 = acc[i][j][0], v1 = acc[i][j][1];
            float v2 = acc[i][j][2], v3 = acc[i][j][3];
            if (Cadd) {
                const float* p0 = Cadd + (size_t)r * ldc + cc;
                const float* p1 = Cadd + (size_t)(r + 8) * ldc + cc;
                v0 += p0[0]; v1 += p0[1]; v2 += p1[0]; v3 += p1[1];
            }
            if (bias) {
                float b0 = bias[cc], b1 = bias[cc + 1];
                v0 += b0; v1 += b1; v2 += b0; v3 += b1;
            }
            if (relu) {
                v0 = fmaxf(v0, 0.f); v1 = fmaxf(v1, 0.f);
                v2 = fmaxf(v2, 0.f); v3 = fmaxf(v3, 0.f);
            }
            *(float2*)(C + (size_t)r * ldc + cc) = make_float2(v0, v1);
            *(float2*)(C + (size_t)(r + 8) * ldc + cc) = make_float2(v2, v3);
        }
    }
}

static void mma_gemm(const float* A, int lda, const float* B, int ldb,
                     float* C, int ldc, const float* Cadd, const float* bias,
                     int M, int N, int K, int relu) {
    dim3 grid(N / 64, M / 64);
    gemm_tf32x3<<<grid, 128>>>(A, lda, B, ldb, C, ldc, Cadd, bias, K, relu);
}

// ---------------- launch ----------------
extern "C" void kernel_launch(void* const* d_in, const int* in_sizes, int n_in,
                              void* d_out, int out_size) {
    if (n_in < 25) return;
    const float* x     = (const float*)d_in[0];
    const float* e0_Wx = (const float*)d_in[1];
    const float* e0_Wh = (const float*)d_in[2];
    const float* e0_b  = (const float*)d_in[3];
    const float* e1_Wx = (const float*)d_in[4];
    const float* e1_Wh = (const float*)d_in[5];
    const float* e1_b  = (const float*)d_in[6];
    const float* d0_Wx = (const float*)d_in[7];
    const float* d0_Wh = (const float*)d_in[8];
    const float* d0_b  = (const float*)d_in[9];
    const float* d1_Wx = (const float*)d_in[10];
    const float* d1_Wh = (const float*)d_in[11];
    const float* d1_b  = (const float*)d_in[12];

    const float* Wm[4] = {0, 0, 0, 0};
    const float* vec[5] = {0, 0, 0, 0, 0};
    const float* fc_W = 0; const float* out_W = 0; const float* out_b = 0;
    int nm = 0, nv = 0;
    for (int i = 13; i < n_in; i++) {
        int sz = in_sizes[i];
        const float* p = (const float*)d_in[i];
        if (sz == HH * HH)           { if (nm < 4) Wm[nm++] = p; }
        else if (sz == HH)           { if (nv < 5) vec[nv++] = p; }
        else if (sz == 2 * HH * HH)  fc_W = p;
        else if (sz == HH * DOUT)    out_W = p;
        else if (sz == DOUT)         out_b = p;
    }
    const float *Wq = Wm[0], *Wk = Wm[1], *Wv = Wm[2], *Wo = Wm[3];
    const float *bq = vec[0], *bk = vec[1], *bv = vec[2], *bo = vec[3], *fc_b = vec[4];

    float *xT, *pre, *y0, *y1, *Kp, *Vp, *z, *c0, *c1, *zeros, *dh0b, *dh1b;
    float *q, *ctx, *att, *comb;
    cudaGetSymbolAddress((void**)&xT, g_xT);
    cudaGetSymbolAddress((void**)&pre, g_pre);
    cudaGetSymbolAddress((void**)&y0, g_y0);
    cudaGetSymbolAddress((void**)&y1, g_y1);
    cudaGetSymbolAddress((void**)&Kp, g_Kp);
    cudaGetSymbolAddress((void**)&Vp, g_Vp);
    cudaGetSymbolAddress((void**)&z, g_z);
    cudaGetSymbolAddress((void**)&c0, g_c0);
    cudaGetSymbolAddress((void**)&c1, g_c1);
    cudaGetSymbolAddress((void**)&zeros, g_zeros);
    cudaGetSymbolAddress((void**)&dh0b, g_dh0);
    cudaGetSymbolAddress((void**)&dh1b, g_dh1);
    cudaGetSymbolAddress((void**)&q, g_q);
    cudaGetSymbolAddress((void**)&ctx, g_ctx);
    cudaGetSymbolAddress((void**)&att, g_att);
    cudaGetSymbolAddress((void**)&comb, g_comb);
    float* dh0[2] = {dh0b, dh0b + BB * HH};
    float* dh1[2] = {dh1b, dh1b + BB * HH};
    float* outp = (float*)d_out;

    const int BH = BB * HH;

    k_zero3<<<(BH + 255) / 256, 256>>>(c0, c1, zeros);

    // ---- encoder layer 0 ----
    k_transpose_x<<<(SS * BB * DIN + 255) / 256, 256>>>(x, xT);
    mma_gemm(xT, DIN, e0_Wx, H4, pre, H4, nullptr, nullptr, SS * BB, H4, DIN, 0);
    for (int t = 0; t < SS; t++) {
        const float* hin = t ? (y0 + (size_t)(t - 1) * BH) : zeros;
        mma_gemm(hin, HH, e0_Wh, H4, z, H4, pre + (size_t)t * BB * H4, nullptr, BB, H4, HH, 0);
        k_gates<<<BH / 256, 256>>>(z, e0_b, c0, y0 + (size_t)t * BH);
    }

    // ---- encoder layer 1 ----
    mma_gemm(y0, HH, e1_Wx, H4, pre, H4, nullptr, nullptr, SS * BB, H4, HH, 0);
    for (int t = 0; t < SS; t++) {
        const float* hin = t ? (y1 + (size_t)(t - 1) * BH) : zeros;
        mma_gemm(hin, HH, e1_Wh, H4, z, H4, pre + (size_t)t * BB * H4, nullptr, BB, H4, HH, 0);
        k_gates<<<BH / 256, 256>>>(z, e1_b, c1, y1 + (size_t)t * BH);
    }

    // ---- K / V projections ----
    mma_gemm(y1, HH, Wk, HH, Kp, HH, nullptr, bk, SS * BB, HH, HH, 0);
    mma_gemm(y1, HH, Wv, HH, Vp, HH, nullptr, bv, SS * BB, HH, HH, 0);

    // ---- decoder ----
    for (int t = 0; t < NSTEPS; t++) {
        const float* xin  = t ? (outp + (t - 1) * DOUT) : zeros;
        int xlda          = t ? (NSTEPS * DOUT) : DOUT;
        const float* h0in = t ? dh0[(t - 1) & 1] : (y0 + (size_t)(SS - 1) * BH);
        const float* h1in = t ? dh1[(t - 1) & 1] : (y1 + (size_t)(SS - 1) * BH);
        float* h0o = dh0[t & 1];
        float* h1o = dh1[t & 1];

        mma_gemm(xin, xlda, d0_Wx, H4, z, H4, nullptr, nullptr, BB, H4, DOUT, 0);
        mma_gemm(h0in, HH, d0_Wh, H4, z, H4, z, nullptr, BB, H4, HH, 0);
        k_gates<<<BH / 256, 256>>>(z, d0_b, c0, h0o);

        mma_gemm(h0o, HH, d1_Wx, H4, z, H4, nullptr, nullptr, BB, H4, HH, 0);
        mma_gemm(h1in, HH, d1_Wh, H4, z, H4, z, nullptr, BB, H4, HH, 0);
        k_gates<<<BH / 256, 256>>>(z, d1_b, c1, h1o);

        mma_gemm(h1o, HH, Wq, HH, q, HH, nullptr, bq, BB, HH, HH, 0);
        k_attn<<<BB * NHEAD, HDIM>>>(q, Kp, Vp, ctx);
        mma_gemm(ctx, HH, Wo, HH, att, HH, nullptr, bo, BB, HH, HH, 0);

        mma_gemm(h1o, HH, fc_W, HH, comb, HH, nullptr, nullptr, BB, HH, HH, 0);
        mma_gemm(att, HH, fc_W + (size_t)HH * HH, HH, comb, HH, comb, fc_b, BB, HH, HH, 1);

        mma_gemm(comb, HH, out_W, DOUT, outp + t * DOUT, NSTEPS * DOUT,
                 nullptr, out_b, BB, DOUT, HH, 0);
    }
}

// round 8
// speedup vs baseline: 1.6584x; 1.6584x over previous
#include <cuda_runtime.h>
#include <cstdint>
#include <stdint.h>
#include <math.h>

#define BB 256
#define SS 128
#define DIN 64
#define DOUT 64
#define HH 1024
#define H4 4096
#define NHEAD 4
#define HDIM 256
#define NSTEPS 16

// ---------------- scratch (static device allocations; no cudaMalloc) ----------------
__device__ float g_xT[SS * BB * DIN];
__device__ float g_pre[SS * BB * H4];
__device__ float g_y0[SS * BB * HH];
__device__ float g_y1[SS * BB * HH];
__device__ float g_Kp[SS * BB * HH];
__device__ float g_Vp[SS * BB * HH];
__device__ float g_z[BB * H4];
__device__ float g_zp[8 * BB * H4];     // split-K partials (up to 8)
__device__ float g_c0[BB * HH];
__device__ float g_c1[BB * HH];
__device__ float g_zeros[BB * HH];
__device__ float g_dh0[2][BB * HH];
__device__ float g_dh1[2][BB * HH];
__device__ float g_q[BB * HH];
__device__ float g_ctx[BB * HH];
__device__ float g_att[BB * HH];
__device__ float g_comb[BB * HH];

// ---------------- small kernels ----------------
__device__ __forceinline__ float sigf(float x) { return 1.0f / (1.0f + expf(-x)); }

__global__ void k_zero3(float* a, float* b, float* c) {
    int i = blockIdx.x * blockDim.x + threadIdx.x;
    if (i < BB * HH) { a[i] = 0.f; b[i] = 0.f; c[i] = 0.f; }
}

__global__ void k_transpose_x(const float* __restrict__ x, float* __restrict__ xT) {
    int i = blockIdx.x * blockDim.x + threadIdx.x;
    if (i >= SS * BB * DIN) return;
    int k = i % DIN;
    int b = (i / DIN) % BB;
    int s = i / (DIN * BB);
    xT[i] = x[(b * SS + s) * DIN + k];
}

// sum np split-K partials (+optional pre) + bias, then LSTM gate nonlinearity
__global__ void k_gatesN(const float* __restrict__ zp, int np,
                         const float* __restrict__ pre,
                         const float* __restrict__ bias,
                         float* __restrict__ c, float* __restrict__ h) {
    int idx = blockIdx.x * blockDim.x + threadIdx.x;
    if (idx >= BB * HH) return;
    int b = idx >> 10;
    int j = idx & (HH - 1);
    size_t base = (size_t)b * H4 + j;
    float zi = 0.f, zf = 0.f, zg = 0.f, zo = 0.f;
    for (int p = 0; p < np; p++) {
        const float* zb = zp + (size_t)p * BB * H4 + base;
        zi += zb[0]; zf += zb[HH]; zg += zb[2 * HH]; zo += zb[3 * HH];
    }
    if (pre) {
        const float* pb = pre + base;
        zi += pb[0]; zf += pb[HH]; zg += pb[2 * HH]; zo += pb[3 * HH];
    }
    zi += bias[j]; zf += bias[HH + j]; zg += bias[2 * HH + j]; zo += bias[3 * HH + j];
    float gi = sigf(zi), gf = sigf(zf), gg = tanhf(zg), go = sigf(zo);
    float cn = gf * c[idx] + gi * gg;
    c[idx] = cn;
    h[idx] = go * tanhf(cn);
}

// sum np split-K partials + bias (+relu), strided dest
__global__ void k_sum(const float* __restrict__ zp, int np, int ncols,
                      const float* __restrict__ bias, float* __restrict__ dst,
                      int ldd, int relu) {
    int idx = blockIdx.x * blockDim.x + threadIdx.x;
    if (idx >= BB * ncols) return;
    int r = idx / ncols;
    int cc = idx - r * ncols;
    float v = 0.f;
    for (int p = 0; p < np; p++) v += zp[(size_t)p * BB * ncols + idx];
    v += bias[cc];
    if (relu) v = fmaxf(v, 0.f);
    dst[(size_t)r * ldd + cc] = v;
}

// one block per (b, head); 256 threads (= HDIM)
__global__ void k_attn(const float* __restrict__ q, const float* __restrict__ Kp,
                       const float* __restrict__ Vp, float* __restrict__ ctx) {
    int b = blockIdx.x / NHEAD;
    int n = blockIdx.x % NHEAD;
    int tid = threadIdx.x;
    int lane = tid & 31;
    int warp = tid >> 5;

    __shared__ float qs[HDIM];
    __shared__ float sc[SS];
    __shared__ float red[8];

    qs[tid] = q[b * HH + n * HDIM + tid];
    __syncthreads();

    for (int s = warp; s < SS; s += 8) {
        const float* kp = Kp + ((size_t)s * BB + b) * HH + n * HDIM;
        float p = 0.f;
        #pragma unroll
        for (int d = lane; d < HDIM; d += 32) p += qs[d] * kp[d];
        #pragma unroll
        for (int o = 16; o > 0; o >>= 1) p += __shfl_xor_sync(0xffffffffu, p, o);
        if (lane == 0) sc[s] = p * (1.0f / 16.0f);
    }
    __syncthreads();

    float v = (tid < SS) ? sc[tid] : -1e30f;
    float m = v;
    #pragma unroll
    for (int o = 16; o > 0; o >>= 1) m = fmaxf(m, __shfl_xor_sync(0xffffffffu, m, o));
    if (lane == 0) red[warp] = m;
    __syncthreads();
    if (tid == 0) {
        float mm = red[0];
        #pragma unroll
        for (int w = 1; w < 8; w++) mm = fmaxf(mm, red[w]);
        red[0] = mm;
    }
    __syncthreads();
    float mx = red[0];
    float e = (tid < SS) ? expf(sc[tid] - mx) : 0.f;
    float ssum = e;
    #pragma unroll
    for (int o = 16; o > 0; o >>= 1) ssum += __shfl_xor_sync(0xffffffffu, ssum, o);
    __syncthreads();
    if (lane == 0) red[warp] = ssum;
    __syncthreads();
    if (tid == 0) {
        float t2 = 0.f;
        #pragma unroll
        for (int w = 0; w < 8; w++) t2 += red[w];
        red[0] = t2;
    }
    __syncthreads();
    float inv = 1.0f / red[0];
    if (tid < SS) sc[tid] = e * inv;
    __syncthreads();

    float acc = 0.f;
    const float* vb = Vp + (size_t)b * HH + n * HDIM + tid;
    for (int s = 0; s < SS; s++) acc += sc[s] * vb[(size_t)s * BB * HH];
    ctx[b * HH + n * HDIM + tid] = acc;
}

// ---------------- 3xTF32 tensor-core GEMM (templated tile, split-K, float2 hi/lo) ----
// C = A@B [+Cadd][+bias][relu].  A row-major [M][lda], B row-major [K][ldb].
// WM = warp rows: BM = WM*32, BN = 64, threads = WM*64, warp tile 32x32, BK = 32.
// blockIdx.z = split-K index; K is the PER-SPLIT depth; partial p writes C + p*cSplitStride.

__device__ __forceinline__ uint32_t cvt_tf32(float x) {
    uint32_t u;
    asm("cvt.rna.tf32.f32 %0, %1;" : "=r"(u) : "f"(x));
    return u;
}

__device__ __forceinline__ void mma8(float* d, const uint32_t* a, const uint32_t* b) {
    asm volatile(
        "mma.sync.aligned.m16n8k8.row.col.f32.tf32.tf32.f32 "
        "{%0,%1,%2,%3},{%4,%5,%6,%7},{%8,%9},{%0,%1,%2,%3};"
        : "+f"(d[0]), "+f"(d[1]), "+f"(d[2]), "+f"(d[3])
        : "r"(a[0]), "r"(a[1]), "r"(a[2]), "r"(a[3]), "r"(b[0]), "r"(b[1]));
}

template <int WM>
__global__ void __launch_bounds__(WM * 64)
gemm_tf32x3(const float* __restrict__ A, int lda,
            const float* __restrict__ B, int ldb,
            float* __restrict__ C, int ldc,
            const float* __restrict__ Cadd,
            const float* __restrict__ bias,
            int K, int relu, long long cSplitStride) {
    constexpr int BM = WM * 32;
    constexpr int THREADS = WM * 64;
    constexpr int LDA_S = BM + 2;
    constexpr int LDB_S = 66;
    extern __shared__ float2 smemBuf[];
    float2* sA = smemBuf;                 // [32][LDA_S] (k, m) -> (hi, lo)
    float2* sB = smemBuf + 32 * LDA_S;    // [32][66]    (k, n) -> (hi, lo)

    // split-K offsets
    A += (size_t)blockIdx.z * K;
    B += (size_t)blockIdx.z * K * ldb;
    C += (size_t)blockIdx.z * cSplitStride;

    const int tid = threadIdx.x;
    const int lane = tid & 31;
    const int warp = tid >> 5;
    const int wm = warp >> 1;
    const int wn = warp & 1;
    const int g = lane >> 2;
    const int tg = lane & 3;
    const int row0 = blockIdx.y * BM;
    const int col0 = blockIdx.x * 64;

    constexpr int NA = BM * 8 / THREADS;   // A tile BM x 32 -> BM*8 float4
    constexpr int NB = 512 / THREADS;      // B tile 32 x 64 -> 512 float4

    int am[NA], ak[NA], bk[NB], bn[NB];
    const float* ap[NA];
    const float* bp[NB];
    #pragma unroll
    for (int i = 0; i < NA; i++) {
        int f = tid + i * THREADS;
        am[i] = f >> 3;
        ak[i] = (f & 7) << 2;
        ap[i] = A + (size_t)(row0 + am[i]) * lda + ak[i];
    }
    #pragma unroll
    for (int i = 0; i < NB; i++) {
        int f = tid + i * THREADS;
        bk[i] = f >> 4;
        bn[i] = (f & 15) << 2;
        bp[i] = B + (size_t)bk[i] * ldb + col0 + bn[i];
    }

    float acc[2][4][4];
    #pragma unroll
    for (int i = 0; i < 2; i++)
        #pragma unroll
        for (int j = 0; j < 4; j++)
            #pragma unroll
            for (int e = 0; e < 4; e++) acc[i][j][e] = 0.f;

    auto stage = [&](float4* va, float4* vb) {
        #pragma unroll
        for (int i = 0; i < NA; i++) {
            float xs[4] = {va[i].x, va[i].y, va[i].z, va[i].w};
            #pragma unroll
            for (int j2 = 0; j2 < 4; j2++) {
                float hi = __uint_as_float(cvt_tf32(xs[j2]));
                float lo = __uint_as_float(cvt_tf32(xs[j2] - hi));
                sA[(ak[i] + j2) * LDA_S + am[i]] = make_float2(hi, lo);
            }
        }
        #pragma unroll
        for (int i = 0; i < NB; i++) {
            float ys[4] = {vb[i].x, vb[i].y, vb[i].z, vb[i].w};
            float hv[4], lv[4];
            #pragma unroll
            for (int j2 = 0; j2 < 4; j2++) {
                hv[j2] = __uint_as_float(cvt_tf32(ys[j2]));
                lv[j2] = __uint_as_float(cvt_tf32(ys[j2] - hv[j2]));
            }
            float2* rowp = sB + bk[i] * LDB_S + bn[i];
            *(float4*)(rowp)     = make_float4(hv[0], lv[0], hv[1], lv[1]);
            *(float4*)(rowp + 2) = make_float4(hv[2], lv[2], hv[3], lv[3]);
        }
    };

    const int nk = K >> 5;

    {
        float4 va[NA], vb[NB];
        #pragma unroll
        for (int i = 0; i < NA; i++) va[i] = *(const float4*)ap[i];
        #pragma unroll
        for (int i = 0; i < NB; i++) vb[i] = *(const float4*)bp[i];
        stage(va, vb);
    }
    __syncthreads();

    for (int c = 0; c < nk; c++) {
        float4 va[NA], vb[NB];
        if (c + 1 < nk) {
            int k0 = (c + 1) << 5;
            #pragma unroll
            for (int i = 0; i < NA; i++) va[i] = *(const float4*)(ap[i] + k0);
            #pragma unroll
            for (int i = 0; i < NB; i++) vb[i] = *(const float4*)(bp[i] + (size_t)k0 * ldb);
        }

        #pragma unroll
        for (int s = 0; s < 4; s++) {
            const int k8 = s * 8;
            uint32_t Ah[2][4], Al[2][4], Bh[4][2], Bl[4][2];
            #pragma unroll
            for (int i = 0; i < 2; i++) {
                int mb = wm * 32 + i * 16;
                float2 f0 = sA[(k8 + tg) * LDA_S + mb + g];
                float2 f1 = sA[(k8 + tg) * LDA_S + mb + g + 8];
                float2 f2 = sA[(k8 + tg + 4) * LDA_S + mb + g];
                float2 f3 = sA[(k8 + tg + 4) * LDA_S + mb + g + 8];
                Ah[i][0] = __float_as_uint(f0.x); Al[i][0] = __float_as_uint(f0.y);
                Ah[i][1] = __float_as_uint(f1.x); Al[i][1] = __float_as_uint(f1.y);
                Ah[i][2] = __float_as_uint(f2.x); Al[i][2] = __float_as_uint(f2.y);
                Ah[i][3] = __float_as_uint(f3.x); Al[i][3] = __float_as_uint(f3.y);
            }
            #pragma unroll
            for (int j = 0; j < 4; j++) {
                int nb = wn * 32 + j * 8;
                float2 f0 = sB[(k8 + tg) * LDB_S + nb + g];
                float2 f1 = sB[(k8 + tg + 4) * LDB_S + nb + g];
                Bh[j][0] = __float_as_uint(f0.x); Bl[j][0] = __float_as_uint(f0.y);
                Bh[j][1] = __float_as_uint(f1.x); Bl[j][1] = __float_as_uint(f1.y);
            }
            #pragma unroll
            for (int i = 0; i < 2; i++)
                #pragma unroll
                for (int j = 0; j < 4; j++) {
                    mma8(acc[i][j], Ah[i], Bl[j]);
                    mma8(acc[i][j], Al[i], Bh[j]);
                    mma8(acc[i][j], Ah[i], Bh[j]);
                }
        }
        __syncthreads();
        if (c + 1 < nk) stage(va, vb);
        __syncthreads();
    }

    #pragma unroll
    for (int i = 0; i < 2; i++) {
        int r = row0 + wm * 32 + i * 16 + g;
        #pragma unroll
        for (int j = 0; j < 4; j++) {
            int cc = col0 + wn * 32 + j * 8 + tg * 2;
            float v0 = acc[i][j][0], v1 = acc[i][j][1];
            float v2 = acc[i][j][2], v3 = acc[i][j][3];
            if (Cadd) {
                const float* p0 = Cadd + (size_t)r * ldc + cc;
                const float* p1 = Cadd + (size_t)(r + 8) * ldc + cc;
                v0 += p0[0]; v1 += p0[1]; v2 += p1[0]; v3 += p1[1];
            }
            if (bias) {
                float b0 = bias[cc], b1 = bias[cc + 1];
                v0 += b0; v1 += b1; v2 += b0; v3 += b1;
            }
            if (relu) {
                v0 = fmaxf(v0, 0.f); v1 = fmaxf(v1, 0.f);
                v2 = fmaxf(v2, 0.f); v3 = fmaxf(v3, 0.f);
            }
            *(float2*)(C + (size_t)r * ldc + cc) = make_float2(v0, v1);
            *(float2*)(C + (size_t)(r + 8) * ldc + cc) = make_float2(v2, v3);
        }
    }
}

static const int SMEM_S = (32 * 66 + 32 * 66) * (int)sizeof(float2);     // 33792
static const int SMEM_L = (32 * 130 + 32 * 66) * (int)sizeof(float2);    // 50176

// small-tile (64x64), optional split-K
static void gemmS(const float* A, int lda, const float* B, int ldb,
                  float* C, int ldc, const float* Cadd, const float* bias,
                  int M, int N, int Ktot, int relu, int splits) {
    dim3 grid(N / 64, M / 64, splits);
    long long cs = (splits > 1) ? (long long)M * N : 0;
    gemm_tf32x3<2><<<grid, 128, SMEM_S>>>(A, lda, B, ldb, C, ldc, Cadd, bias,
                                          Ktot / splits, relu, cs);
}
// large-tile (128x64) for big M
static void gemmL(const float* A, int lda, const float* B, int ldb,
                  float* C, int ldc, const float* Cadd, const float* bias,
                  int M, int N, int K, int relu) {
    dim3 grid(N / 64, M / 128, 1);
    gemm_tf32x3<4><<<grid, 256, SMEM_L>>>(A, lda, B, ldb, C, ldc, Cadd, bias, K, relu, 0);
}

// ---------------- launch ----------------
extern "C" void kernel_launch(void* const* d_in, const int* in_sizes, int n_in,
                              void* d_out, int out_size) {
    if (n_in < 25) return;
    cudaFuncSetAttribute(gemm_tf32x3<2>, cudaFuncAttributeMaxDynamicSharedMemorySize, SMEM_S);
    cudaFuncSetAttribute(gemm_tf32x3<4>, cudaFuncAttributeMaxDynamicSharedMemorySize, SMEM_L);

    const float* x     = (const float*)d_in[0];
    const float* e0_Wx = (const float*)d_in[1];
    const float* e0_Wh = (const float*)d_in[2];
    const float* e0_b  = (const float*)d_in[3];
    const float* e1_Wx = (const float*)d_in[4];
    const float* e1_Wh = (const float*)d_in[5];
    const float* e1_b  = (const float*)d_in[6];
    const float* d0_Wx = (const float*)d_in[7];
    const float* d0_Wh = (const float*)d_in[8];
    const float* d0_b  = (const float*)d_in[9];
    const float* d1_Wx = (const float*)d_in[10];
    const float* d1_Wh = (const float*)d_in[11];
    const float* d1_b  = (const float*)d_in[12];

    const float* Wm[4] = {0, 0, 0, 0};
    const float* vec[5] = {0, 0, 0, 0, 0};
    const float* fc_W = 0; const float* out_W = 0; const float* out_b = 0;
    int nm = 0, nv = 0;
    for (int i = 13; i < n_in; i++) {
        int sz = in_sizes[i];
        const float* p = (const float*)d_in[i];
        if (sz == HH * HH)           { if (nm < 4) Wm[nm++] = p; }
        else if (sz == HH)           { if (nv < 5) vec[nv++] = p; }
        else if (sz == 2 * HH * HH)  fc_W = p;
        else if (sz == HH * DOUT)    out_W = p;
        else if (sz == DOUT)         out_b = p;
    }
    const float *Wq = Wm[0], *Wk = Wm[1], *Wv = Wm[2], *Wo = Wm[3];
    const float *bq = vec[0], *bk = vec[1], *bv = vec[2], *bo = vec[3], *fc_b = vec[4];

    float *xT, *pre, *y0, *y1, *Kp, *Vp, *z, *zp, *c0, *c1, *zeros, *dh0b, *dh1b;
    float *q, *ctx, *att, *comb;
    cudaGetSymbolAddress((void**)&xT, g_xT);
    cudaGetSymbolAddress((void**)&pre, g_pre);
    cudaGetSymbolAddress((void**)&y0, g_y0);
    cudaGetSymbolAddress((void**)&y1, g_y1);
    cudaGetSymbolAddress((void**)&Kp, g_Kp);
    cudaGetSymbolAddress((void**)&Vp, g_Vp);
    cudaGetSymbolAddress((void**)&z, g_z);
    cudaGetSymbolAddress((void**)&zp, g_zp);
    cudaGetSymbolAddress((void**)&c0, g_c0);
    cudaGetSymbolAddress((void**)&c1, g_c1);
    cudaGetSymbolAddress((void**)&zeros, g_zeros);
    cudaGetSymbolAddress((void**)&dh0b, g_dh0);
    cudaGetSymbolAddress((void**)&dh1b, g_dh1);
    cudaGetSymbolAddress((void**)&q, g_q);
    cudaGetSymbolAddress((void**)&ctx, g_ctx);
    cudaGetSymbolAddress((void**)&att, g_att);
    cudaGetSymbolAddress((void**)&comb, g_comb);
    float* dh0[2] = {dh0b, dh0b + BB * HH};
    float* dh1[2] = {dh1b, dh1b + BB * HH};
    float* outp = (float*)d_out;

    const int BH = BB * HH;
    const int GB = BH / 256;   // blocks for elementwise over B*H

    k_zero3<<<GB, 256>>>(c0, c1, zeros);

    // ---- encoder layer 0 ----
    k_transpose_x<<<(SS * BB * DIN + 255) / 256, 256>>>(x, xT);
    gemmL(xT, DIN, e0_Wx, H4, pre, H4, nullptr, nullptr, SS * BB, H4, DIN, 0);
    for (int t = 0; t < SS; t++) {
        const float* hin = t ? (y0 + (size_t)(t - 1) * BH) : zeros;
        gemmS(hin, HH, e0_Wh, H4, zp, H4, nullptr, nullptr, BB, H4, HH, 0, 4);
        k_gatesN<<<GB, 256>>>(zp, 4, pre + (size_t)t * BB * H4, e0_b, c0, y0 + (size_t)t * BH);
    }

    // ---- encoder layer 1 ----
    gemmL(y0, HH, e1_Wx, H4, pre, H4, nullptr, nullptr, SS * BB, H4, HH, 0);
    for (int t = 0; t < SS; t++) {
        const float* hin = t ? (y1 + (size_t)(t - 1) * BH) : zeros;
        gemmS(hin, HH, e1_Wh, H4, zp, H4, nullptr, nullptr, BB, H4, HH, 0, 4);
        k_gatesN<<<GB, 256>>>(zp, 4, pre + (size_t)t * BB * H4, e1_b, c1, y1 + (size_t)t * BH);
    }

    // ---- K / V projections ----
    gemmL(y1, HH, Wk, HH, Kp, HH, nullptr, bk, SS * BB, HH, HH, 0);
    gemmL(y1, HH, Wv, HH, Vp, HH, nullptr, bv, SS * BB, HH, HH, 0);

    // ---- decoder ----
    for (int t = 0; t < NSTEPS; t++) {
        const float* xin  = t ? (outp + (t - 1) * DOUT) : zeros;
        int xlda          = t ? (NSTEPS * DOUT) : DOUT;
        const float* h0in = t ? dh0[(t - 1) & 1] : (y0 + (size_t)(SS - 1) * BH);
        const float* h1in = t ? dh1[(t - 1) & 1] : (y1 + (size_t)(SS - 1) * BH);
        float* h0o = dh0[t & 1];
        float* h1o = dh1[t & 1];

        // cell d0: z = xin@Wx (direct) ; h@Wh split-K4 ; gates sums all
        gemmS(xin, xlda, d0_Wx, H4, z, H4, nullptr, nullptr, BB, H4, DOUT, 0, 1);
        gemmS(h0in, HH, d0_Wh, H4, zp, H4, nullptr, nullptr, BB, H4, HH, 0, 4);
        k_gatesN<<<GB, 256>>>(zp, 4, z, d0_b, c0, h0o);

        // cell d1: split-K4 each of h0o@Wx and h1@Wh -> 8 partials
        gemmS(h0o, HH, d1_Wx, H4, zp, H4, nullptr, nullptr, BB, H4, HH, 0, 4);
        gemmS(h1in, HH, d1_Wh, H4, zp + 4 * (size_t)BB * H4, H4, nullptr, nullptr, BB, H4, HH, 0, 4);
        k_gatesN<<<GB, 256>>>(zp, 8, nullptr, d1_b, c1, h1o);

        // attention: q projection split-K4 + sum
        gemmS(h1o, HH, Wq, HH, zp, HH, nullptr, nullptr, BB, HH, HH, 0, 4);
        k_sum<<<GB, 256>>>(zp, 4, HH, bq, q, HH, 0);
        k_attn<<<BB * NHEAD, HDIM>>>(q, Kp, Vp, ctx);
        gemmS(ctx, HH, Wo, HH, zp, HH, nullptr, nullptr, BB, HH, HH, 0, 4);
        k_sum<<<GB, 256>>>(zp, 4, HH, bo, att, HH, 0);

        // comb = relu([h1o, att] @ fc_W + fc_b): two split-K4 GEMMs -> 8 partials
        gemmS(h1o, HH, fc_W, HH, zp, HH, nullptr, nullptr, BB, HH, HH, 0, 4);
        gemmS(att, HH, fc_W + (size_t)HH * HH, HH, zp + 4 * (size_t)BB * HH, HH,
              nullptr, nullptr, BB, HH, HH, 0, 4);
        k_sum<<<GB, 256>>>(zp, 8, HH, fc_b, comb, HH, 1);

        // out[:, t, :] = comb @ out_W + out_b  (split-K8, tiny N)
        gemmS(comb, HH, out_W, DOUT, zp, DOUT, nullptr, nullptr, BB, DOUT, HH, 0, 8);
        k_sum<<<(BB * DOUT + 255) / 256, 256>>>(zp, 8, DOUT, out_b, outp + t * DOUT,
                                                NSTEPS * DOUT, 0);
    }
}

// round 10
// speedup vs baseline: 2.0872x; 1.2586x over previous
#include <cuda_runtime.h>
#include <cstdint>
#include <stdint.h>
#include <math.h>

#define BB 256
#define SS 128
#define DIN 64
#define DOUT 64
#define HH 1024
#define H4 4096
#define NHEAD 4
#define HDIM 256
#define NSTEPS 16
#define MM (SS * BB)      // 32768

// ---------------- fp32 scratch ----------------
__device__ float g_pre[MM * H4];          // 512 MB
__device__ float g_z[BB * H4];
__device__ float g_zp[8 * BB * H4];
__device__ float g_c0[BB * HH];
__device__ float g_c1[BB * HH];
__device__ float g_q[BB * HH];
__device__ float g_Kp[MM * HH];
__device__ float g_Vp[MM * HH];

// ---------------- pre-split float2 buffers (hi, lo) ----------------
__device__ __align__(16) float2 g_e0Wxs[DIN * H4];
__device__ __align__(16) float2 g_e0Whs[HH * H4];
__device__ __align__(16) float2 g_e1Wxs[HH * H4];
__device__ __align__(16) float2 g_e1Whs[HH * H4];
__device__ __align__(16) float2 g_d0Wxs[DOUT * H4];
__device__ __align__(16) float2 g_d0Whs[HH * H4];
__device__ __align__(16) float2 g_d1Wxs[HH * H4];
__device__ __align__(16) float2 g_d1Whs[HH * H4];
__device__ __align__(16) float2 g_Wqs[HH * HH];
__device__ __align__(16) float2 g_Wks[HH * HH];
__device__ __align__(16) float2 g_Wvs[HH * HH];
__device__ __align__(16) float2 g_Wos[HH * HH];
__device__ __align__(16) float2 g_fcWs[2 * HH * HH];
__device__ __align__(16) float2 g_outWs[HH * DOUT];
// A-side transposed split layouts: [k][m]
__device__ __align__(16) float2 g_xTs[DIN * MM];
__device__ __align__(16) float2 g_y0Ts[HH * MM];
__device__ __align__(16) float2 g_y1Ts[HH * MM];
__device__ __align__(16) float2 g_zerosTs[HH * BB];
__device__ __align__(16) float2 g_dh0Ts[2][HH * BB];
__device__ __align__(16) float2 g_dh1Ts[2][HH * BB];
__device__ __align__(16) float2 g_ctxTs[HH * BB];
__device__ __align__(16) float2 g_attTs[HH * BB];
__device__ __align__(16) float2 g_combTs[HH * BB];
__device__ __align__(16) float2 g_outTs[DOUT * BB];

// ---------------- helpers ----------------
__device__ __forceinline__ float sigf(float x) { return 1.0f / (1.0f + expf(-x)); }

__device__ __forceinline__ uint32_t cvt_tf32(float x) {
    uint32_t u;
    asm("cvt.rna.tf32.f32 %0, %1;" : "=r"(u) : "f"(x));
    return u;
}
__device__ __forceinline__ float2 split2(float x) {
    float hi = __uint_as_float(cvt_tf32(x));
    float lo = __uint_as_float(cvt_tf32(x - hi));
    return make_float2(hi, lo);
}
__device__ __forceinline__ uint32_t smem_u32(const void* p) {
    uint32_t r;
    asm("{ .reg .u64 t; cvta.to.shared.u64 t, %1; cvt.u32.u64 %0, t; }" : "=r"(r) : "l"(p));
    return r;
}
__device__ __forceinline__ void cpasync16(uint32_t dst, const void* src) {
    asm volatile("cp.async.cg.shared.global [%0], [%1], 16;\n" :: "r"(dst), "l"(src));
}

// ---------------- small kernels ----------------
__global__ void k_split(const float* __restrict__ w, float2* __restrict__ ws, int n) {
    int i = blockIdx.x * blockDim.x + threadIdx.x;
    if (i < n) ws[i] = split2(w[i]);
}

__global__ void k_init(float* c0, float* c1, float2* zTs) {
    int i = blockIdx.x * blockDim.x + threadIdx.x;
    if (i < BB * HH) { c0[i] = 0.f; c1[i] = 0.f; zTs[i] = make_float2(0.f, 0.f); }
}

// x[b][s][k] -> xTs[k][s*256+b] split   (FIXED index decomposition: k = i >> 15)
__global__ void k_split_x(const float* __restrict__ x, float2* __restrict__ xTs) {
    int i = blockIdx.x * blockDim.x + threadIdx.x;
    if (i >= MM * DIN) return;
    int m = i & (MM - 1);          // bits 0..14
    int b = m & (BB - 1);
    int s = m >> 8;
    int k = i >> 15;
    xTs[(size_t)k * MM + m] = split2(x[(b * SS + s) * DIN + k]);
}

// sum np split-K partials (+opt pre) + bias -> LSTM gates; h written split-transposed
__global__ void k_gatesN(const float* __restrict__ zp, int np,
                         const float* __restrict__ pre,
                         const float* __restrict__ bias,
                         float* __restrict__ c,
                         float2* __restrict__ hTs, int ldm) {
    int idx = blockIdx.x * blockDim.x + threadIdx.x;
    if (idx >= BB * HH) return;
    int b = idx >> 10;
    int j = idx & (HH - 1);
    size_t base = (size_t)b * H4 + j;
    float zi = 0.f, zf = 0.f, zg = 0.f, zo = 0.f;
    for (int p = 0; p < np; p++) {
        const float* zb = zp + (size_t)p * BB * H4 + base;
        zi += zb[0]; zf += zb[HH]; zg += zb[2 * HH]; zo += zb[3 * HH];
    }
    if (pre) {
        const float* pb = pre + base;
        zi += pb[0]; zf += pb[HH]; zg += pb[2 * HH]; zo += pb[3 * HH];
    }
    zi += bias[j]; zf += bias[HH + j]; zg += bias[2 * HH + j]; zo += bias[3 * HH + j];
    float gi = sigf(zi), gf = sigf(zf), gg = tanhf(zg), go = sigf(zo);
    float cn = gf * c[idx] + gi * gg;
    c[idx] = cn;
    float hv = go * tanhf(cn);
    hTs[(size_t)j * ldm + b] = split2(hv);
}

// sum partials + bias (+relu); optional plain strided dst, optional split-T dst
__global__ void k_sum(const float* __restrict__ zp, int np, int ncols,
                      const float* __restrict__ bias,
                      float* __restrict__ dst, int ldd, int relu,
                      float2* __restrict__ dstTs, int ldm) {
    int idx = blockIdx.x * blockDim.x + threadIdx.x;
    if (idx >= BB * ncols) return;
    int r = idx / ncols;
    int cc = idx - r * ncols;
    float v = 0.f;
    for (int p = 0; p < np; p++) v += zp[(size_t)p * BB * ncols + idx];
    v += bias[cc];
    if (relu) v = fmaxf(v, 0.f);
    if (dst) dst[(size_t)r * ldd + cc] = v;
    if (dstTs) dstTs[(size_t)cc * ldm + r] = split2(v);
}

// one block per (b, head); 256 threads
__global__ void k_attn(const float* __restrict__ q, const float* __restrict__ Kp,
                       const float* __restrict__ Vp, float2* __restrict__ ctxTs) {
    int b = blockIdx.x / NHEAD;
    int n = blockIdx.x % NHEAD;
    int tid = threadIdx.x;
    int lane = tid & 31;
    int warp = tid >> 5;

    __shared__ float qs[HDIM];
    __shared__ float sc[SS];
    __shared__ float red[8];

    qs[tid] = q[b * HH + n * HDIM + tid];
    __syncthreads();

    for (int s = warp; s < SS; s += 8) {
        const float* kp = Kp + ((size_t)s * BB + b) * HH + n * HDIM;
        float p = 0.f;
        #pragma unroll
        for (int d = lane; d < HDIM; d += 32) p += qs[d] * kp[d];
        #pragma unroll
        for (int o = 16; o > 0; o >>= 1) p += __shfl_xor_sync(0xffffffffu, p, o);
        if (lane == 0) sc[s] = p * (1.0f / 16.0f);
    }
    __syncthreads();

    float v = (tid < SS) ? sc[tid] : -1e30f;
    float m = v;
    #pragma unroll
    for (int o = 16; o > 0; o >>= 1) m = fmaxf(m, __shfl_xor_sync(0xffffffffu, m, o));
    if (lane == 0) red[warp] = m;
    __syncthreads();
    if (tid == 0) {
        float mm = red[0];
        #pragma unroll
        for (int w = 1; w < 8; w++) mm = fmaxf(mm, red[w]);
        red[0] = mm;
    }
    __syncthreads();
    float mx = red[0];
    float e = (tid < SS) ? expf(sc[tid] - mx) : 0.f;
    float ssum = e;
    #pragma unroll
    for (int o = 16; o > 0; o >>= 1) ssum += __shfl_xor_sync(0xffffffffu, ssum, o);
    __syncthreads();
    if (lane == 0) red[warp] = ssum;
    __syncthreads();
    if (tid == 0) {
        float t2 = 0.f;
        #pragma unroll
        for (int w = 0; w < 8; w++) t2 += red[w];
        red[0] = t2;
    }
    __syncthreads();
    float inv = 1.0f / red[0];
    if (tid < SS) sc[tid] = e * inv;
    __syncthreads();

    float acc = 0.f;
    const float* vb = Vp + (size_t)b * HH + n * HDIM + tid;
    for (int s = 0; s < SS; s++) acc += sc[s] * vb[(size_t)s * BB * HH];
    ctxTs[(size_t)(n * HDIM + tid) * BB + b] = split2(acc);
}

// ---------------- pre-split 3xTF32 GEMM with cp.async double buffering ----------
// A: split, TRANSPOSED [K][lda] float2 (A[k][m]).  B: split [K][ldb] float2.
// C = A^T(as M x K) @ B, fp32 out [M][ldc] (+bias)(+relu).
// Tile 64x64, BK=16, 128 threads = 4 warps (2x2 of 32x32 warp tiles).
// blockIdx.z = split-K; K is per-split depth; partial z -> C + z*cSplitStride.

__device__ __forceinline__ void mma8(float* d, const uint32_t* a, const uint32_t* b) {
    asm volatile(
        "mma.sync.aligned.m16n8k8.row.col.f32.tf32.tf32.f32 "
        "{%0,%1,%2,%3},{%4,%5,%6,%7},{%8,%9},{%0,%1,%2,%3};"
        : "+f"(d[0]), "+f"(d[1]), "+f"(d[2]), "+f"(d[3])
        : "r"(a[0]), "r"(a[1]), "r"(a[2]), "r"(a[3]), "r"(b[0]), "r"(b[1]));
}

#define LDS_ 66

__global__ void __launch_bounds__(128, 4)
gemmP(const float2* __restrict__ A, int lda,
      const float2* __restrict__ B, int ldb,
      float* __restrict__ C, int ldc,
      const float* __restrict__ bias,
      int K, int relu, long long cSplitStride) {
    extern __shared__ float2 sm[];
    float2* sA = sm;                       // [2][16][LDS_]
    float2* sB = sm + 2 * 16 * LDS_;       // [2][16][LDS_]

    A += (size_t)blockIdx.z * K * lda;
    B += (size_t)blockIdx.z * K * ldb;
    C += (size_t)blockIdx.z * cSplitStride;

    const int tid = threadIdx.x;
    const int lane = tid & 31;
    const int warp = tid >> 5;
    const int wm = warp >> 1;
    const int wn = warp & 1;
    const int g = lane >> 2;
    const int tg = lane & 3;
    const int row0 = blockIdx.y * 64;
    const int col0 = blockIdx.x * 64;

    // cp.async mapping: 512 chunks of 16B per operand per stage; 4 per thread
    int rr[4], c2[4];
    #pragma unroll
    for (int i = 0; i < 4; i++) {
        int c = tid + i * 128;
        rr[i] = c >> 5;
        c2[i] = (c & 31) * 2;
    }
    const float2* aSrc = A + row0;
    const float2* bSrc = B + col0;
    const uint32_t saBase = smem_u32(sA);
    const uint32_t sbBase = smem_u32(sB);

    float acc[2][4][4];
    #pragma unroll
    for (int i = 0; i < 2; i++)
        #pragma unroll
        for (int j = 0; j < 4; j++)
            #pragma unroll
            for (int e = 0; e < 4; e++) acc[i][j][e] = 0.f;

    const int nk = K >> 4;

    // prologue: stage 0
    #pragma unroll
    for (int i = 0; i < 4; i++) {
        cpasync16(saBase + (uint32_t)(rr[i] * LDS_ + c2[i]) * 8,
                  aSrc + (size_t)rr[i] * lda + c2[i]);
        cpasync16(sbBase + (uint32_t)(rr[i] * LDS_ + c2[i]) * 8,
                  bSrc + (size_t)rr[i] * ldb + c2[i]);
    }
    asm volatile("cp.async.commit_group;\n" ::: "memory");

    for (int c = 0; c < nk; c++) {
        if (c + 1 < nk) {
            int st = (c + 1) & 1;
            int k0 = (c + 1) << 4;
            uint32_t aOff = saBase + (uint32_t)(st * 16 * LDS_) * 8;
            uint32_t bOff = sbBase + (uint32_t)(st * 16 * LDS_) * 8;
            #pragma unroll
            for (int i = 0; i < 4; i++) {
                cpasync16(aOff + (uint32_t)(rr[i] * LDS_ + c2[i]) * 8,
                          aSrc + (size_t)(k0 + rr[i]) * lda + c2[i]);
                cpasync16(bOff + (uint32_t)(rr[i] * LDS_ + c2[i]) * 8,
                          bSrc + (size_t)(k0 + rr[i]) * ldb + c2[i]);
            }
            asm volatile("cp.async.commit_group;\n" ::: "memory");
            asm volatile("cp.async.wait_group 1;\n" ::: "memory");
        } else {
            asm volatile("cp.async.wait_group 0;\n" ::: "memory");
        }
        __syncthreads();

        const float2* SA = sA + (c & 1) * 16 * LDS_;
        const float2* SB = sB + (c & 1) * 16 * LDS_;
        #pragma unroll
        for (int s = 0; s < 2; s++) {
            const int k8 = s * 8;
            uint32_t Ah[2][4], Al[2][4], Bh[4][2], Bl[4][2];
            #pragma unroll
            for (int i = 0; i < 2; i++) {
                int mb = wm * 32 + i * 16;
                float2 f0 = SA[(k8 + tg) * LDS_ + mb + g];
                float2 f1 = SA[(k8 + tg) * LDS_ + mb + g + 8];
                float2 f2 = SA[(k8 + tg + 4) * LDS_ + mb + g];
                float2 f3 = SA[(k8 + tg + 4) * LDS_ + mb + g + 8];
                Ah[i][0] = __float_as_uint(f0.x); Al[i][0] = __float_as_uint(f0.y);
                Ah[i][1] = __float_as_uint(f1.x); Al[i][1] = __float_as_uint(f1.y);
                Ah[i][2] = __float_as_uint(f2.x); Al[i][2] = __float_as_uint(f2.y);
                Ah[i][3] = __float_as_uint(f3.x); Al[i][3] = __float_as_uint(f3.y);
            }
            #pragma unroll
            for (int j = 0; j < 4; j++) {
                int nb = wn * 32 + j * 8;
                float2 f0 = SB[(k8 + tg) * LDS_ + nb + g];
                float2 f1 = SB[(k8 + tg + 4) * LDS_ + nb + g];
                Bh[j][0] = __float_as_uint(f0.x); Bl[j][0] = __float_as_uint(f0.y);
                Bh[j][1] = __float_as_uint(f1.x); Bl[j][1] = __float_as_uint(f1.y);
            }
            #pragma unroll
            for (int i = 0; i < 2; i++)
                #pragma unroll
                for (int j = 0; j < 4; j++) {
                    mma8(acc[i][j], Ah[i], Bl[j]);
                    mma8(acc[i][j], Al[i], Bh[j]);
                    mma8(acc[i][j], Ah[i], Bh[j]);
                }
        }
        __syncthreads();
    }

    #pragma unroll
    for (int i = 0; i < 2; i++) {
        int r = row0 + wm * 32 + i * 16 + g;
        #pragma unroll
        for (int j = 0; j < 4; j++) {
            int cc = col0 + wn * 32 + j * 8 + tg * 2;
            float v0 = acc[i][j][0], v1 = acc[i][j][1];
            float v2 = acc[i][j][2], v3 = acc[i][j][3];
            if (bias) {
                float b0 = bias[cc], b1 = bias[cc + 1];
                v0 += b0; v1 += b1; v2 += b0; v3 += b1;
            }
            if (relu) {
                v0 = fmaxf(v0, 0.f); v1 = fmaxf(v1, 0.f);
                v2 = fmaxf(v2, 0.f); v3 = fmaxf(v3, 0.f);
            }
            *(float2*)(C + (size_t)r * ldc + cc) = make_float2(v0, v1);
            *(float2*)(C + (size_t)(r + 8) * ldc + cc) = make_float2(v2, v3);
        }
    }
}

static const int SMEMP = 4 * 16 * LDS_ * (int)sizeof(float2);  // 33792

static void gP(const float2* A, int lda, const float2* B, int ldb,
               float* C, int ldc, const float* bias,
               int M, int N, int Ktot, int relu, int splits) {
    dim3 grid(N / 64, M / 64, splits);
    long long cs = (splits > 1) ? (long long)M * N : 0;
    gemmP<<<grid, 128, SMEMP>>>(A, lda, B, ldb, C, ldc, bias, Ktot / splits, relu, cs);
}

// ---------------- launch ----------------
extern "C" void kernel_launch(void* const* d_in, const int* in_sizes, int n_in,
                              void* d_out, int out_size) {
    if (n_in < 25) return;

    const float* x     = (const float*)d_in[0];
    const float* wsrc[14];
    wsrc[0] = (const float*)d_in[1];   // e0_Wx
    wsrc[1] = (const float*)d_in[2];   // e0_Wh
    const float* e0_b  = (const float*)d_in[3];
    wsrc[2] = (const float*)d_in[4];   // e1_Wx
    wsrc[3] = (const float*)d_in[5];   // e1_Wh
    const float* e1_b  = (const float*)d_in[6];
    wsrc[4] = (const float*)d_in[7];   // d0_Wx
    wsrc[5] = (const float*)d_in[8];   // d0_Wh
    const float* d0_b  = (const float*)d_in[9];
    wsrc[6] = (const float*)d_in[10];  // d1_Wx
    wsrc[7] = (const float*)d_in[11];  // d1_Wh
    const float* d1_b  = (const float*)d_in[12];

    const float* Wm[4] = {0, 0, 0, 0};
    const float* vec[5] = {0, 0, 0, 0, 0};
    const float* fc_W = 0; const float* out_W = 0; const float* out_b = 0;
    int nm = 0, nv = 0;
    for (int i = 13; i < n_in; i++) {
        int sz = in_sizes[i];
        const float* p = (const float*)d_in[i];
        if (sz == HH * HH)           { if (nm < 4) Wm[nm++] = p; }
        else if (sz == HH)           { if (nv < 5) vec[nv++] = p; }
        else if (sz == 2 * HH * HH)  fc_W = p;
        else if (sz == HH * DOUT)    out_W = p;
        else if (sz == DOUT)         out_b = p;
    }
    wsrc[8] = Wm[0]; wsrc[9] = Wm[1]; wsrc[10] = Wm[2]; wsrc[11] = Wm[3];
    wsrc[12] = fc_W; wsrc[13] = out_W;
    const float *bq = vec[0], *bk = vec[1], *bv = vec[2], *bo = vec[3], *fc_b = vec[4];

    float *pre, *z, *zp, *c0, *c1, *q, *Kp, *Vp;
    float2 *e0Wxs, *e0Whs, *e1Wxs, *e1Whs, *d0Wxs, *d0Whs, *d1Wxs, *d1Whs;
    float2 *Wqs, *Wks, *Wvs, *Wos, *fcWs, *outWs;
    float2 *xTs, *y0Ts, *y1Ts, *zerosTs, *dh0Tsb, *dh1Tsb, *ctxTs, *attTs, *combTs, *outTs;
    cudaGetSymbolAddress((void**)&pre, g_pre);
    cudaGetSymbolAddress((void**)&z, g_z);
    cudaGetSymbolAddress((void**)&zp, g_zp);
    cudaGetSymbolAddress((void**)&c0, g_c0);
    cudaGetSymbolAddress((void**)&c1, g_c1);
    cudaGetSymbolAddress((void**)&q, g_q);
    cudaGetSymbolAddress((void**)&Kp, g_Kp);
    cudaGetSymbolAddress((void**)&Vp, g_Vp);
    cudaGetSymbolAddress((void**)&e0Wxs, g_e0Wxs);
    cudaGetSymbolAddress((void**)&e0Whs, g_e0Whs);
    cudaGetSymbolAddress((void**)&e1Wxs, g_e1Wxs);
    cudaGetSymbolAddress((void**)&e1Whs, g_e1Whs);
    cudaGetSymbolAddress((void**)&d0Wxs, g_d0Wxs);
    cudaGetSymbolAddress((void**)&d0Whs, g_d0Whs);
    cudaGetSymbolAddress((void**)&d1Wxs, g_d1Wxs);
    cudaGetSymbolAddress((void**)&d1Whs, g_d1Whs);
    cudaGetSymbolAddress((void**)&Wqs, g_Wqs);
    cudaGetSymbolAddress((void**)&Wks, g_Wks);
    cudaGetSymbolAddress((void**)&Wvs, g_Wvs);
    cudaGetSymbolAddress((void**)&Wos, g_Wos);
    cudaGetSymbolAddress((void**)&fcWs, g_fcWs);
    cudaGetSymbolAddress((void**)&outWs, g_outWs);
    cudaGetSymbolAddress((void**)&xTs, g_xTs);
    cudaGetSymbolAddress((void**)&y0Ts, g_y0Ts);
    cudaGetSymbolAddress((void**)&y1Ts, g_y1Ts);
    cudaGetSymbolAddress((void**)&zerosTs, g_zerosTs);
    cudaGetSymbolAddress((void**)&dh0Tsb, g_dh0Ts);
    cudaGetSymbolAddress((void**)&dh1Tsb, g_dh1Ts);
    cudaGetSymbolAddress((void**)&ctxTs, g_ctxTs);
    cudaGetSymbolAddress((void**)&attTs, g_attTs);
    cudaGetSymbolAddress((void**)&combTs, g_combTs);
    cudaGetSymbolAddress((void**)&outTs, g_outTs);
    float2* wdst[14] = {e0Wxs, e0Whs, e1Wxs, e1Whs, d0Wxs, d0Whs, d1Wxs, d1Whs,
                        Wqs, Wks, Wvs, Wos, fcWs, outWs};
    int wcnt[14] = {DIN * H4, HH * H4, HH * H4, HH * H4, DOUT * H4, HH * H4, HH * H4, HH * H4,
                    HH * HH, HH * HH, HH * HH, HH * HH, 2 * HH * HH, HH * DOUT};
    float2* dh0Ts[2] = {dh0Tsb, dh0Tsb + HH * BB};
    float2* dh1Ts[2] = {dh1Tsb, dh1Tsb + HH * BB};
    float* outp = (float*)d_out;

    const int BH = BB * HH;
    const int GB = BH / 256;

    // one-time-per-replay prep: zero state, split weights + x
    k_init<<<GB, 256>>>(c0, c1, zerosTs);
    for (int i = 0; i < 14; i++)
        k_split<<<(wcnt[i] + 255) / 256, 256>>>(wsrc[i], wdst[i], wcnt[i]);
    k_split_x<<<(MM * DIN + 255) / 256, 256>>>(x, xTs);

    // ---- encoder layer 0 ----
    gP(xTs, MM, e0Wxs, H4, pre, H4, nullptr, MM, H4, DIN, 0, 1);
    for (int t = 0; t < SS; t++) {
        const float2* hin = t ? (y0Ts + (size_t)(t - 1) * BB) : zerosTs;
        int hlda = t ? MM : BB;
        gP(hin, hlda, e0Whs, H4, zp, H4, nullptr, BB, H4, HH, 0, 4);
        k_gatesN<<<GB, 256>>>(zp, 4, pre + (size_t)t * BB * H4, e0_b, c0,
                              y0Ts + (size_t)t * BB, MM);
    }

    // ---- encoder layer 1 ----
    gP(y0Ts, MM, e1Wxs, H4, pre, H4, nullptr, MM, H4, HH, 0, 1);
    for (int t = 0; t < SS; t++) {
        const float2* hin = t ? (y1Ts + (size_t)(t - 1) * BB) : zerosTs;
        int hlda = t ? MM : BB;
        gP(hin, hlda, e1Whs, H4, zp, H4, nullptr, BB, H4, HH, 0, 4);
        k_gatesN<<<GB, 256>>>(zp, 4, pre + (size_t)t * BB * H4, e1_b, c1,
                              y1Ts + (size_t)t * BB, MM);
    }

    // ---- K / V projections ----
    gP(y1Ts, MM, Wks, HH, Kp, HH, bk, MM, HH, HH, 0, 1);
    gP(y1Ts, MM, Wvs, HH, Vp, HH, bv, MM, HH, HH, 0, 1);

    // ---- decoder ----
    for (int t = 0; t < NSTEPS; t++) {
        const float2* xin  = t ? outTs : zerosTs;
        const float2* h0in = t ? dh0Ts[(t - 1) & 1] : (y0Ts + (size_t)(SS - 1) * BB);
        int h0lda          = t ? BB : MM;
        const float2* h1in = t ? dh1Ts[(t - 1) & 1] : (y1Ts + (size_t)(SS - 1) * BB);
        int h1lda          = t ? BB : MM;

        // cell d0
        gP(xin, BB, d0Wxs, H4, z, H4, nullptr, BB, H4, DOUT, 0, 1);
        gP(h0in, h0lda, d0Whs, H4, zp, H4, nullptr, BB, H4, HH, 0, 4);
        k_gatesN<<<GB, 256>>>(zp, 4, z, d0_b, c0, dh0Ts[t & 1], BB);

        // cell d1
        gP(dh0Ts[t & 1], BB, d1Wxs, H4, zp, H4, nullptr, BB, H4, HH, 0, 4);
        gP(h1in, h1lda, d1Whs, H4, zp + 4 * (size_t)BB * H4, H4, nullptr, BB, H4, HH, 0, 4);
        k_gatesN<<<GB, 256>>>(zp, 8, nullptr, d1_b, c1, dh1Ts[t & 1], BB);

        // attention
        gP(dh1Ts[t & 1], BB, Wqs, HH, zp, HH, nullptr, BB, HH, HH, 0, 4);
        k_sum<<<GB, 256>>>(zp, 4, HH, bq, q, HH, 0, nullptr, 0);
        k_attn<<<BB * NHEAD, HDIM>>>(q, Kp, Vp, ctxTs);
        gP(ctxTs, BB, Wos, HH, zp, HH, nullptr, BB, HH, HH, 0, 4);
        k_sum<<<GB, 256>>>(zp, 4, HH, bo, nullptr, 0, 0, attTs, BB);

        // comb = relu([h1, att] @ fc_W + fc_b)
        gP(dh1Ts[t & 1], BB, fcWs, HH, zp, HH, nullptr, BB, HH, HH, 0, 4);
        gP(attTs, BB, fcWs + (size_t)HH * HH, HH, zp + 4 * (size_t)BB * HH, HH,
           nullptr, BB, HH, HH, 0, 4);
        k_sum<<<GB, 256>>>(zp, 8, HH, fc_b, nullptr, 0, 1, combTs, BB);

        // out
        gP(combTs, BB, outWs, DOUT, zp, DOUT, nullptr, BB, DOUT, HH, 0, 8);
        k_sum<<<(BB * DOUT + 255) / 256, 256>>>(zp, 8, DOUT, out_b,
                                                outp + t * DOUT, NSTEPS * DOUT, 0,
                                                outTs, BB);
    }
}

// round 14
// speedup vs baseline: 4.4051x; 2.1106x over previous
#include <cuda_runtime.h>
#include <cuda_bf16.h>
#include <cstdint>
#include <stdint.h>
#include <math.h>

#define BB 256
#define SS 128
#define DIN 64
#define DOUT 64
#define HH 1024
#define H4 4096
#define NHEAD 4
#define HDIM 256
#define NSTEPS 16
#define MM (SS * BB)      // 32768

// ---------------- fp32 scratch ----------------
__device__ float g_pre[MM * H4];
__device__ float g_z[BB * H4];
__device__ float g_zp[8 * BB * H4];
__device__ float g_c0[BB * HH];
__device__ float g_c1[BB * HH];
__device__ float g_q[BB * HH];
__device__ float g_Kp[MM * HH];
__device__ float g_Vp[MM * HH];

// ---------------- bf16 split planes: [0]=hi, [1]=lo ; k-pair packed uint32 ------
__device__ __align__(16) uint32_t g_e0Wxs[2][DIN / 2 * H4];
__device__ __align__(16) uint32_t g_e0Whs[2][HH / 2 * H4];
__device__ __align__(16) uint32_t g_e1Wxs[2][HH / 2 * H4];
__device__ __align__(16) uint32_t g_e1Whs[2][HH / 2 * H4];
__device__ __align__(16) uint32_t g_d0Wxs[2][DOUT / 2 * H4];
__device__ __align__(16) uint32_t g_d0Whs[2][HH / 2 * H4];
__device__ __align__(16) uint32_t g_d1Wxs[2][HH / 2 * H4];
__device__ __align__(16) uint32_t g_d1Whs[2][HH / 2 * H4];
__device__ __align__(16) uint32_t g_Wqs[2][HH / 2 * HH];
__device__ __align__(16) uint32_t g_Wks[2][HH / 2 * HH];
__device__ __align__(16) uint32_t g_Wvs[2][HH / 2 * HH];
__device__ __align__(16) uint32_t g_Wos[2][HH / 2 * HH];
__device__ __align__(16) uint32_t g_fcWs[2][HH * HH];          // K=2048 -> 1024 kp rows
__device__ __align__(16) uint32_t g_outWs[2][HH / 2 * DOUT];
// A-side transposed planes [kp][m]
__device__ __align__(16) uint32_t g_xTs[2][DIN / 2 * MM];
__device__ __align__(16) uint32_t g_y0Ts[2][HH / 2 * MM];
__device__ __align__(16) uint32_t g_y1Ts[2][HH / 2 * MM];
__device__ __align__(16) uint32_t g_zerosTs[2][HH / 2 * BB];
__device__ __align__(16) uint32_t g_dh0Ts[2][2][HH / 2 * BB];
__device__ __align__(16) uint32_t g_dh1Ts[2][2][HH / 2 * BB];
__device__ __align__(16) uint32_t g_ctxTs[2][HH / 2 * BB];
__device__ __align__(16) uint32_t g_attTs[2][HH / 2 * BB];
__device__ __align__(16) uint32_t g_combTs[2][HH / 2 * BB];
__device__ __align__(16) uint32_t g_outTs[2][DOUT / 2 * BB];

// ---------------- helpers ----------------
__device__ __forceinline__ float sigf(float x) { return 1.0f / (1.0f + expf(-x)); }

__device__ __forceinline__ void splitpack(float x0, float x1, uint32_t& whi, uint32_t& wlo) {
    __nv_bfloat16 h0 = __float2bfloat16(x0), h1 = __float2bfloat16(x1);
    float r0 = x0 - __bfloat162float(h0);
    float r1 = x1 - __bfloat162float(h1);
    __nv_bfloat16 l0 = __float2bfloat16(r0), l1 = __float2bfloat16(r1);
    whi = ((uint32_t)__bfloat16_as_ushort(h1) << 16) | __bfloat16_as_ushort(h0);
    wlo = ((uint32_t)__bfloat16_as_ushort(l1) << 16) | __bfloat16_as_ushort(l0);
}
// single-element bf16 split write into planes viewed as ushort
__device__ __forceinline__ void split_store1(float x, unsigned short* hiU, unsigned short* loU,
                                             int k, int m, int ldm) {
    __nv_bfloat16 h = __float2bfloat16(x);
    float r = x - __bfloat162float(h);
    int idx = 2 * ((k >> 1) * ldm + m) + (k & 1);
    hiU[idx] = __bfloat16_as_ushort(h);
    loU[idx] = __bfloat16_as_ushort(__float2bfloat16(r));
}
__device__ __forceinline__ uint32_t smem_u32(const void* p) {
    uint32_t r;
    asm("{ .reg .u64 t; cvta.to.shared.u64 t, %1; cvt.u32.u64 %0, t; }" : "=r"(r) : "l"(p));
    return r;
}
__device__ __forceinline__ void cpasync16(uint32_t dst, const void* src) {
    asm volatile("cp.async.cg.shared.global [%0], [%1], 16;\n" :: "r"(dst), "l"(src));
}

// ---------------- small kernels ----------------
// weight split: w [K][N] fp32 -> planes [K/2][N] packed; N = 1<<nshift
__global__ void k_split_w(const float* __restrict__ w, uint32_t* __restrict__ hi,
                          uint32_t* __restrict__ lo, int halfn, int nshift) {
    int i = blockIdx.x * blockDim.x + threadIdx.x;
    if (i >= halfn) return;
    int kp = i >> nshift;
    int n = i & ((1 << nshift) - 1);
    float x0 = w[(size_t)(2 * kp) * (1 << nshift) + n];
    float x1 = w[(size_t)(2 * kp + 1) * (1 << nshift) + n];
    splitpack(x0, x1, hi[i], lo[i]);
}

__global__ void k_init(float* c0, float* c1, uint32_t* zh, uint32_t* zl) {
    int i = blockIdx.x * blockDim.x + threadIdx.x;
    if (i < BB * HH) { c0[i] = 0.f; c1[i] = 0.f; }
    if (i < BB * HH / 2) { zh[i] = 0u; zl[i] = 0u; }
}

// x[b][s][k] -> planes [kp][m], m = s*256+b
__global__ void k_split_x(const float* __restrict__ x, uint32_t* __restrict__ hi,
                          uint32_t* __restrict__ lo) {
    int i = blockIdx.x * blockDim.x + threadIdx.x;
    if (i >= DIN / 2 * MM) return;
    int m = i & (MM - 1);
    int b = m & (BB - 1);
    int s = m >> 8;
    int kp = i >> 15;
    const float* src = x + (size_t)(b * SS + s) * DIN + 2 * kp;
    splitpack(src[0], src[1], hi[i], lo[i]);
}

// sum np partials (+opt pre) + bias -> LSTM gates; h -> split planes
__global__ void k_gatesN(const float* __restrict__ zp, int np,
                         const float* __restrict__ pre,
                         const float* __restrict__ bias,
                         float* __restrict__ c,
                         unsigned short* __restrict__ hiT,
                         unsigned short* __restrict__ loT, int ldm) {
    int idx = blockIdx.x * blockDim.x + threadIdx.x;
    if (idx >= BB * HH) return;
    int b = idx >> 10;
    int j = idx & (HH - 1);
    size_t base = (size_t)b * H4 + j;
    float zi = 0.f, zf = 0.f, zg = 0.f, zo = 0.f;
    for (int p = 0; p < np; p++) {
        const float* zb = zp + (size_t)p * BB * H4 + base;
        zi += zb[0]; zf += zb[HH]; zg += zb[2 * HH]; zo += zb[3 * HH];
    }
    if (pre) {
        const float* pb = pre + base;
        zi += pb[0]; zf += pb[HH]; zg += pb[2 * HH]; zo += pb[3 * HH];
    }
    zi += bias[j]; zf += bias[HH + j]; zg += bias[2 * HH + j]; zo += bias[3 * HH + j];
    float gi = sigf(zi), gf = sigf(zf), gg = tanhf(zg), go = sigf(zo);
    float cn = gf * c[idx] + gi * gg;
    c[idx] = cn;
    split_store1(go * tanhf(cn), hiT, loT, j, b, ldm);
}

// sum partials + bias (+relu); optional fp32 dst, optional split-plane dst
__global__ void k_sum(const float* __restrict__ zp, int np, int ncols,
                      const float* __restrict__ bias,
                      float* __restrict__ dst, int ldd, int relu,
                      unsigned short* __restrict__ hiT,
                      unsigned short* __restrict__ loT, int ldm) {
    int idx = blockIdx.x * blockDim.x + threadIdx.x;
    if (idx >= BB * ncols) return;
    int r = idx / ncols;
    int cc = idx - r * ncols;
    float v = 0.f;
    for (int p = 0; p < np; p++) v += zp[(size_t)p * BB * ncols + idx];
    v += bias[cc];
    if (relu) v = fmaxf(v, 0.f);
    if (dst) dst[(size_t)r * ldd + cc] = v;
    if (hiT) split_store1(v, hiT, loT, cc, r, ldm);
}

// one block per (b, head); 256 threads
__global__ void k_attn(const float* __restrict__ q, const float* __restrict__ Kp,
                       const float* __restrict__ Vp,
                       unsigned short* __restrict__ hiT, unsigned short* __restrict__ loT) {
    int b = blockIdx.x / NHEAD;
    int n = blockIdx.x % NHEAD;
    int tid = threadIdx.x;
    int lane = tid & 31;
    int warp = tid >> 5;

    __shared__ float qs[HDIM];
    __shared__ float sc[SS];
    __shared__ float red[8];

    qs[tid] = q[b * HH + n * HDIM + tid];
    __syncthreads();

    for (int s = warp; s < SS; s += 8) {
        const float* kp = Kp + ((size_t)s * BB + b) * HH + n * HDIM;
        float p = 0.f;
        #pragma unroll
        for (int d = lane; d < HDIM; d += 32) p += qs[d] * kp[d];
        #pragma unroll
        for (int o = 16; o > 0; o >>= 1) p += __shfl_xor_sync(0xffffffffu, p, o);
        if (lane == 0) sc[s] = p * (1.0f / 16.0f);
    }
    __syncthreads();

    float v = (tid < SS) ? sc[tid] : -1e30f;
    float m = v;
    #pragma unroll
    for (int o = 16; o > 0; o >>= 1) m = fmaxf(m, __shfl_xor_sync(0xffffffffu, m, o));
    if (lane == 0) red[warp] = m;
    __syncthreads();
    if (tid == 0) {
        float mm = red[0];
        #pragma unroll
        for (int w = 1; w < 8; w++) mm = fmaxf(mm, red[w]);
        red[0] = mm;
    }
    __syncthreads();
    float mx = red[0];
    float e = (tid < SS) ? expf(sc[tid] - mx) : 0.f;
    float ssum = e;
    #pragma unroll
    for (int o = 16; o > 0; o >>= 1) ssum += __shfl_xor_sync(0xffffffffu, ssum, o);
    __syncthreads();
    if (lane == 0) red[warp] = ssum;
    __syncthreads();
    if (tid == 0) {
        float t2 = 0.f;
        #pragma unroll
        for (int w = 0; w < 8; w++) t2 += red[w];
        red[0] = t2;
    }
    __syncthreads();
    float inv = 1.0f / red[0];
    if (tid < SS) sc[tid] = e * inv;
    __syncthreads();

    float acc = 0.f;
    const float* vb = Vp + (size_t)b * HH + n * HDIM + tid;
    for (int s = 0; s < SS; s++) acc += sc[s] * vb[(size_t)s * BB * HH];
    split_store1(acc, hiT, loT, n * HDIM + tid, b, BB);
}

// ---------------- bf16x3 GEMM (pre-split planes, cp.async double buffering) ----
// A planes [kp][lda] packed (logical A[m][k], transposed).  B planes [kp][ldb].
// C = A^T @ B fp32 [M][ldc] (+bias)(+relu).  Tile 64x64, BK=32, 128 thr, 4 warps.
// blockIdx.z = split-K; K per-split; partial z -> C + z*cSplitStride.

__device__ __forceinline__ void mma16(float* d, const uint32_t* a, const uint32_t* b) {
    asm volatile(
        "mma.sync.aligned.m16n8k16.row.col.f32.bf16.bf16.f32 "
        "{%0,%1,%2,%3},{%4,%5,%6,%7},{%8,%9},{%0,%1,%2,%3};"
        : "+f"(d[0]), "+f"(d[1]), "+f"(d[2]), "+f"(d[3])
        : "r"(a[0]), "r"(a[1]), "r"(a[2]), "r"(a[3]), "r"(b[0]), "r"(b[1]));
}

#define LDSU 72
#define PLN (16 * LDSU)           // words per plane per stage (16 kp rows)

__global__ void __launch_bounds__(128, 4)
gemmB(const uint32_t* __restrict__ Ah, const uint32_t* __restrict__ Al, int lda,
      const uint32_t* __restrict__ Bh, const uint32_t* __restrict__ Bl, int ldb,
      float* __restrict__ C, int ldc,
      const float* __restrict__ bias,
      int K, int relu, long long cSplitStride) {
    extern __shared__ uint32_t smw[];   // [2 stages][4 planes][PLN]

    const int kpSplit = (K >> 1);
    Ah += (size_t)blockIdx.z * kpSplit * lda;
    Al += (size_t)blockIdx.z * kpSplit * lda;
    Bh += (size_t)blockIdx.z * kpSplit * ldb;
    Bl += (size_t)blockIdx.z * kpSplit * ldb;
    C += (size_t)blockIdx.z * cSplitStride;

    const int tid = threadIdx.x;
    const int lane = tid & 31;
    const int warp = tid >> 5;
    const int wm = warp >> 1;
    const int wn = warp & 1;
    const int g = lane >> 2;
    const int tg = lane & 3;
    const int row0 = blockIdx.y * 64;
    const int col0 = blockIdx.x * 64;

    const uint32_t smBase = smem_u32(smw);
    const uint32_t* aH = Ah + row0;
    const uint32_t* aL = Al + row0;
    const uint32_t* bH = Bh + col0;
    const uint32_t* bL = Bl + col0;

    // per-thread cp.async chunks: 2 per plane (256 chunks/plane / 128 thr)
    int r1 = tid >> 4, o1 = (tid & 15) * 4;
    int r2 = (tid + 128) >> 4, o2 = ((tid + 128) & 15) * 4;

    auto fill = [&](int st, int kp0) {
        uint32_t base = smBase + (uint32_t)(st * 4 * PLN) * 4;
        cpasync16(base + (uint32_t)(r1 * LDSU + o1) * 4, aH + (size_t)(kp0 + r1) * lda + o1);
        cpasync16(base + (uint32_t)(r2 * LDSU + o2) * 4, aH + (size_t)(kp0 + r2) * lda + o2);
        cpasync16(base + (uint32_t)(PLN + r1 * LDSU + o1) * 4, aL + (size_t)(kp0 + r1) * lda + o1);
        cpasync16(base + (uint32_t)(PLN + r2 * LDSU + o2) * 4, aL + (size_t)(kp0 + r2) * lda + o2);
        cpasync16(base + (uint32_t)(2 * PLN + r1 * LDSU + o1) * 4, bH + (size_t)(kp0 + r1) * ldb + o1);
        cpasync16(base + (uint32_t)(2 * PLN + r2 * LDSU + o2) * 4, bH + (size_t)(kp0 + r2) * ldb + o2);
        cpasync16(base + (uint32_t)(3 * PLN + r1 * LDSU + o1) * 4, bL + (size_t)(kp0 + r1) * ldb + o1);
        cpasync16(base + (uint32_t)(3 * PLN + r2 * LDSU + o2) * 4, bL + (size_t)(kp0 + r2) * ldb + o2);
        asm volatile("cp.async.commit_group;\n" ::: "memory");
    };

    float acc[2][4][4];
    #pragma unroll
    for (int i = 0; i < 2; i++)
        #pragma unroll
        for (int j = 0; j < 4; j++)
            #pragma unroll
            for (int e = 0; e < 4; e++) acc[i][j][e] = 0.f;

    const int nk = K >> 5;   // BK=32 -> 16 kp rows per stage

    fill(0, 0);

    for (int c = 0; c < nk; c++) {
        if (c + 1 < nk) {
            fill((c + 1) & 1, (c + 1) * 16);
            asm volatile("cp.async.wait_group 1;\n" ::: "memory");
        } else {
            asm volatile("cp.async.wait_group 0;\n" ::: "memory");
        }
        __syncthreads();

        const uint32_t* SAh = smw + (c & 1) * 4 * PLN;
        const uint32_t* SAl = SAh + PLN;
        const uint32_t* SBh = SAh + 2 * PLN;
        const uint32_t* SBl = SAh + 3 * PLN;

        #pragma unroll
        for (int s = 0; s < 2; s++) {       // two k16 chunks: kp rows s*8 + {tg, tg+4}
            const int kb = s * 8;
            uint32_t AhF[2][4], AlF[2][4], BhF[4][2], BlF[4][2];
            #pragma unroll
            for (int i = 0; i < 2; i++) {
                int mb = wm * 32 + i * 16;
                AhF[i][0] = SAh[(kb + tg) * LDSU + mb + g];
                AhF[i][1] = SAh[(kb + tg) * LDSU + mb + g + 8];
                AhF[i][2] = SAh[(kb + tg + 4) * LDSU + mb + g];
                AhF[i][3] = SAh[(kb + tg + 4) * LDSU + mb + g + 8];
                AlF[i][0] = SAl[(kb + tg) * LDSU + mb + g];
                AlF[i][1] = SAl[(kb + tg) * LDSU + mb + g + 8];
                AlF[i][2] = SAl[(kb + tg + 4) * LDSU + mb + g];
                AlF[i][3] = SAl[(kb + tg + 4) * LDSU + mb + g + 8];
            }
            #pragma unroll
            for (int j = 0; j < 4; j++) {
                int cb = wn * 32 + j * 8 + g;
                BhF[j][0] = SBh[(kb + tg) * LDSU + cb];
                BhF[j][1] = SBh[(kb + tg + 4) * LDSU + cb];
                BlF[j][0] = SBl[(kb + tg) * LDSU + cb];
                BlF[j][1] = SBl[(kb + tg + 4) * LDSU + cb];
            }
            #pragma unroll
            for (int i = 0; i < 2; i++)
                #pragma unroll
                for (int j = 0; j < 4; j++) {
                    mma16(acc[i][j], AhF[i], BlF[j]);
                    mma16(acc[i][j], AlF[i], BhF[j]);
                    mma16(acc[i][j], AhF[i], BhF[j]);
                }
        }
        __syncthreads();
    }

    #pragma unroll
    for (int i = 0; i < 2; i++) {
        int r = row0 + wm * 32 + i * 16 + g;
        #pragma unroll
        for (int j = 0; j < 4; j++) {
            int cc = col0 + wn * 32 + j * 8 + tg * 2;
            float v0 = acc[i][j][0], v1 = acc[i][j][1];
            float v2 = acc[i][j][2], v3 = acc[i][j][3];
            if (bias) {
                float b0 = bias[cc], b1 = bias[cc + 1];
                v0 += b0; v1 += b1; v2 += b0; v3 += b1;
            }
            if (relu) {
                v0 = fmaxf(v0, 0.f); v1 = fmaxf(v1, 0.f);
                v2 = fmaxf(v2, 0.f); v3 = fmaxf(v3, 0.f);
            }
            *(float2*)(C + (size_t)r * ldc + cc) = make_float2(v0, v1);
            *(float2*)(C + (size_t)(r + 8) * ldc + cc) = make_float2(v2, v3);
        }
    }
}

static const int SMEMB = 2 * 4 * PLN * (int)sizeof(uint32_t);   // 36864

struct Pl { const uint32_t* hi; const uint32_t* lo; };

static void gB(Pl A, int lda, Pl B, int ldb, float* C, int ldc, const float* bias,
               int M, int N, int Ktot, int relu, int splits) {
    dim3 grid(N / 64, M / 64, splits);
    long long cs = (splits > 1) ? (long long)M * N : 0;
    gemmB<<<grid, 128, SMEMB>>>(A.hi, A.lo, lda, B.hi, B.lo, ldb, C, ldc, bias,
                                Ktot / splits, relu, cs);
}

// ---------------- launch ----------------
extern "C" void kernel_launch(void* const* d_in, const int* in_sizes, int n_in,
                              void* d_out, int out_size) {
    if (n_in < 25) return;
    cudaFuncSetAttribute(gemmB, cudaFuncAttributeMaxDynamicSharedMemorySize, SMEMB);

    const float* x     = (const float*)d_in[0];
    const float* wsrc[14];
    wsrc[0] = (const float*)d_in[1];
    wsrc[1] = (const float*)d_in[2];
    const float* e0_b  = (const float*)d_in[3];
    wsrc[2] = (const float*)d_in[4];
    wsrc[3] = (const float*)d_in[5];
    const float* e1_b  = (const float*)d_in[6];
    wsrc[4] = (const float*)d_in[7];
    wsrc[5] = (const float*)d_in[8];
    const float* d0_b  = (const float*)d_in[9];
    wsrc[6] = (const float*)d_in[10];
    wsrc[7] = (const float*)d_in[11];
    const float* d1_b  = (const float*)d_in[12];

    const float* Wm[4] = {0, 0, 0, 0};
    const float* vec[5] = {0, 0, 0, 0, 0};
    const float* fc_W = 0; const float* out_W = 0; const float* out_b = 0;
    int nm = 0, nv = 0;
    for (int i = 13; i < n_in; i++) {
        int sz = in_sizes[i];
        const float* p = (const float*)d_in[i];
        if (sz == HH * HH)           { if (nm < 4) Wm[nm++] = p; }
        else if (sz == HH)           { if (nv < 5) vec[nv++] = p; }
        else if (sz == 2 * HH * HH)  fc_W = p;
        else if (sz == HH * DOUT)    out_W = p;
        else if (sz == DOUT)         out_b = p;
    }
    wsrc[8] = Wm[0]; wsrc[9] = Wm[1]; wsrc[10] = Wm[2]; wsrc[11] = Wm[3];
    wsrc[12] = fc_W; wsrc[13] = out_W;
    const float *bq = vec[0], *bk = vec[1], *bv = vec[2], *bo = vec[3], *fc_b = vec[4];

    float *pre, *z, *zp, *c0, *c1, *q, *Kp, *Vp;
    cudaGetSymbolAddress((void**)&pre, g_pre);
    cudaGetSymbolAddress((void**)&z, g_z);
    cudaGetSymbolAddress((void**)&zp, g_zp);
    cudaGetSymbolAddress((void**)&c0, g_c0);
    cudaGetSymbolAddress((void**)&c1, g_c1);
    cudaGetSymbolAddress((void**)&q, g_q);
    cudaGetSymbolAddress((void**)&Kp, g_Kp);
    cudaGetSymbolAddress((void**)&Vp, g_Vp);

    uint32_t* wbuf[14];
    cudaGetSymbolAddress((void**)&wbuf[0], g_e0Wxs);
    cudaGetSymbolAddress((void**)&wbuf[1], g_e0Whs);
    cudaGetSymbolAddress((void**)&wbuf[2], g_e1Wxs);
    cudaGetSymbolAddress((void**)&wbuf[3], g_e1Whs);
    cudaGetSymbolAddress((void**)&wbuf[4], g_d0Wxs);
    cudaGetSymbolAddress((void**)&wbuf[5], g_d0Whs);
    cudaGetSymbolAddress((void**)&wbuf[6], g_d1Wxs);
    cudaGetSymbolAddress((void**)&wbuf[7], g_d1Whs);
    cudaGetSymbolAddress((void**)&wbuf[8], g_Wqs);
    cudaGetSymbolAddress((void**)&wbuf[9], g_Wks);
    cudaGetSymbolAddress((void**)&wbuf[10], g_Wvs);
    cudaGetSymbolAddress((void**)&wbuf[11], g_Wos);
    cudaGetSymbolAddress((void**)&wbuf[12], g_fcWs);
    cudaGetSymbolAddress((void**)&wbuf[13], g_outWs);
    // halfn counts and N shifts
    int whalf[14] = {DIN / 2 * H4, HH / 2 * H4, HH / 2 * H4, HH / 2 * H4,
                     DOUT / 2 * H4, HH / 2 * H4, HH / 2 * H4, HH / 2 * H4,
                     HH / 2 * HH, HH / 2 * HH, HH / 2 * HH, HH / 2 * HH,
                     HH * HH, HH / 2 * DOUT};
    int wshift[14] = {12, 12, 12, 12, 12, 12, 12, 12, 10, 10, 10, 10, 10, 6};

    uint32_t *xTb, *y0b, *y1b, *zb, *dh0b, *dh1b, *ctxb, *attb, *combb, *outb;
    cudaGetSymbolAddress((void**)&xTb, g_xTs);
    cudaGetSymbolAddress((void**)&y0b, g_y0Ts);
    cudaGetSymbolAddress((void**)&y1b, g_y1Ts);
    cudaGetSymbolAddress((void**)&zb, g_zerosTs);
    cudaGetSymbolAddress((void**)&dh0b, g_dh0Ts);
    cudaGetSymbolAddress((void**)&dh1b, g_dh1Ts);
    cudaGetSymbolAddress((void**)&ctxb, g_ctxTs);
    cudaGetSymbolAddress((void**)&attb, g_attTs);
    cudaGetSymbolAddress((void**)&combb, g_combTs);
    cudaGetSymbolAddress((void**)&outb, g_outTs);

    const int HB2 = HH / 2 * BB;
    Pl Wpl[14];
    for (int i = 0; i < 14; i++) Wpl[i] = Pl{wbuf[i], wbuf[i] + whalf[i]};
    Pl xT{xTb, xTb + DIN / 2 * MM};
    Pl y0{y0b, y0b + HH / 2 * MM};
    Pl y1{y1b, y1b + HH / 2 * MM};
    Pl zerosT{zb, zb + HB2};
    Pl dh0T[2] = {Pl{dh0b, dh0b + HB2}, Pl{dh0b + 2 * HB2, dh0b + 3 * HB2}};
    Pl dh1T[2] = {Pl{dh1b, dh1b + HB2}, Pl{dh1b + 2 * HB2, dh1b + 3 * HB2}};
    Pl ctxT{ctxb, ctxb + HB2};
    Pl attT{attb, attb + HB2};
    Pl combT{combb, combb + HB2};
    Pl outT{outb, outb + DOUT / 2 * BB};
    float* outp = (float*)d_out;

    const int BH = BB * HH;
    const int GB = BH / 256;
    auto US = [](const uint32_t* p) { return (unsigned short*)p; };

    // prep: zero state, split weights + x
    k_init<<<GB, 256>>>(c0, c1, (uint32_t*)zerosT.hi, (uint32_t*)zerosT.lo);
    for (int i = 0; i < 14; i++)
        k_split_w<<<(whalf[i] + 255) / 256, 256>>>(wsrc[i], (uint32_t*)Wpl[i].hi,
                                                   (uint32_t*)Wpl[i].lo, whalf[i], wshift[i]);
    k_split_x<<<(DIN / 2 * MM + 255) / 256, 256>>>(x, (uint32_t*)xT.hi, (uint32_t*)xT.lo);

    // ---- encoder layer 0 ----
    gB(xT, MM, Wpl[0], H4, pre, H4, nullptr, MM, H4, DIN, 0, 1);
    for (int t = 0; t < SS; t++) {
        Pl hin = t ? Pl{y0.hi + (size_t)(t - 1) * BB, y0.lo + (size_t)(t - 1) * BB} : zerosT;
        int hlda = t ? MM : BB;
        gB(hin, hlda, Wpl[1], H4, zp, H4, nullptr, BB, H4, HH, 0, 4);
        k_gatesN<<<GB, 256>>>(zp, 4, pre + (size_t)t * BB * H4, e0_b, c0,
                              US(y0.hi) + (size_t)2 * t * BB, US(y0.lo) + (size_t)2 * t * BB, MM);
    }

    // ---- encoder layer 1 ----
    gB(y0, MM, Wpl[2], H4, pre, H4, nullptr, MM, H4, HH, 0, 1);
    for (int t = 0; t < SS; t++) {
        Pl hin = t ? Pl{y1.hi + (size_t)(t - 1) * BB, y1.lo + (size_t)(t - 1) * BB} : zerosT;
        int hlda = t ? MM : BB;
        gB(hin, hlda, Wpl[3], H4, zp, H4, nullptr, BB, H4, HH, 0, 4);
        k_gatesN<<<GB, 256>>>(zp, 4, pre + (size_t)t * BB * H4, e1_b, c1,
                              US(y1.hi) + (size_t)2 * t * BB, US(y1.lo) + (size_t)2 * t * BB, MM);
    }

    // ---- K / V projections ----
    gB(y1, MM, Wpl[9], HH, Kp, HH, bk, MM, HH, HH, 0, 1);
    gB(y1, MM, Wpl[10], HH, Vp, HH, bv, MM, HH, HH, 0, 1);

    // ---- decoder ----
    for (int t = 0; t < NSTEPS; t++) {
        Pl xin  = t ? outT : zerosT;
        Pl h0in = t ? dh0T[(t - 1) & 1]
                    : Pl{y0.hi + (size_t)(SS - 1) * BB, y0.lo + (size_t)(SS - 1) * BB};
        int h0lda = t ? BB : MM;
        Pl h1in = t ? dh1T[(t - 1) & 1]
                    : Pl{y1.hi + (size_t)(SS - 1) * BB, y1.lo + (size_t)(SS - 1) * BB};
        int h1lda = t ? BB : MM;

        // cell d0
        gB(xin, BB, Wpl[4], H4, z, H4, nullptr, BB, H4, DOUT, 0, 1);
        gB(h0in, h0lda, Wpl[5], H4, zp, H4, nullptr, BB, H4, HH, 0, 4);
        k_gatesN<<<GB, 256>>>(zp, 4, z, d0_b, c0,
                              US(dh0T[t & 1].hi), US(dh0T[t & 1].lo), BB);

        // cell d1
        gB(dh0T[t & 1], BB, Wpl[6], H4, zp, H4, nullptr, BB, H4, HH, 0, 4);
        gB(h1in, h1lda, Wpl[7], H4, zp + 4 * (size_t)BB * H4, H4, nullptr, BB, H4, HH, 0, 4);
        k_gatesN<<<GB, 256>>>(zp, 8, nullptr, d1_b, c1,
                              US(dh1T[t & 1].hi), US(dh1T[t & 1].lo), BB);

        // attention
        gB(dh1T[t & 1], BB, Wpl[8], HH, zp, HH, nullptr, BB, HH, HH, 0, 4);
        k_sum<<<GB, 256>>>(zp, 4, HH, bq, q, HH, 0, nullptr, nullptr, 0);
        k_attn<<<BB * NHEAD, HDIM>>>(q, Kp, Vp, US(ctxT.hi), US(ctxT.lo));
        gB(ctxT, BB, Wpl[11], HH, zp, HH, nullptr, BB, HH, HH, 0, 4);
        k_sum<<<GB, 256>>>(zp, 4, HH, bo, nullptr, 0, 0, US(attT.hi), US(attT.lo), BB);

        // comb = relu([h1, att] @ fc_W + fc_b) ; fc second half offset = (1024/2)*HH words
        gB(dh1T[t & 1], BB, Wpl[12], HH, zp, HH, nullptr, BB, HH, HH, 0, 4);
        Pl fc2{Wpl[12].hi + (size_t)512 * HH, Wpl[12].lo + (size_t)512 * HH};
        gB(attT, BB, fc2, HH, zp + 4 * (size_t)BB * HH, HH, nullptr, BB, HH, HH, 0, 4);
        k_sum<<<GB, 256>>>(zp, 8, HH, fc_b, nullptr, 0, 1, US(combT.hi), US(combT.lo), BB);

        // out
        gB(combT, BB, Wpl[13], DOUT, zp, DOUT, nullptr, BB, DOUT, HH, 0, 8);
        k_sum<<<(BB * DOUT + 255) / 256, 256>>>(zp, 8, DOUT, out_b,
                                                outp + t * DOUT, NSTEPS * DOUT, 0,
                                                US(outT.hi), US(outT.lo), BB);
    }
}